// round 7
// baseline (speedup 1.0000x reference)
#include <cuda_runtime.h>

#define B_  64
#define T_  1024
#define A_  128
#define F_  1024
#define KC_ 31
#define DQ_ 1024
#define DV_ 512
#define J_  62          // KC_ * 2 channels
#define NC  16          // t-chunks for S partials
#define TC  (T_/NC)     // 64
#define BT  64          // t-tile of main kernel
#define BK  16          // k-tile of main GEMM

// ---- scratch (device globals: no allocation allowed) ----
__device__ float g_v [B_*T_*A_];        // tanh(value @ Wm)  : 33.5M floats
__device__ float g_q [B_*A_];           // tanh(query @ Wq)
__device__ float g_e [B_*T_];           // pre-softmax scores
__device__ float g_S [B_*J_*A_];        // shifted-correlation factor
__device__ float g_Sp[B_*NC*J_*A_];     // deterministic partials for g_S

__device__ __forceinline__ float ftanh(float x) {
    // tanh(x) = 1 - 2/(exp(2x)+1); __expf/__fdividef error ~1e-6 rel.
    float e = __expf(2.0f * x);
    return 1.0f - __fdividef(2.0f, e + 1.0f);
}

// ---------------- kernel 1: q = tanh(query @ Wq) ----------------
__global__ __launch_bounds__(128) void kq(const float* __restrict__ query,
                                          const float* __restrict__ Wq) {
    int b = blockIdx.x;
    int a = threadIdx.x;                    // 128 threads = A
    __shared__ float qs[DQ_];
    for (int d = a; d < DQ_; d += 128) qs[d] = query[b*DQ_ + d];
    __syncthreads();
    float acc = 0.0f;
    #pragma unroll 8
    for (int d = 0; d < DQ_; d++) acc = fmaf(qs[d], Wq[d*A_ + a], acc);
    g_q[b*A_ + a] = ftanh(acc);
}

// ------- kernel 2: S partials. S[b,j=2k+c,a] = sum_t aw[b,t+k-15,c]*Wloc[t,a] -------
__global__ __launch_bounds__(128) void kS(const float* __restrict__ aw,
                                          const float* __restrict__ Wloc) {
    int b  = blockIdx.x;
    int ch = blockIdx.y;
    int a  = threadIdx.x;                   // 128
    int t0 = ch * TC;

    __shared__ float awm[2][TC + KC_ - 1];  // halo window [t0-15, t0+TC+14]
    for (int i = threadIdx.x; i < 2*(TC + KC_ - 1); i += 128) {
        int c = i / (TC + KC_ - 1);
        int off = i % (TC + KC_ - 1);
        int t = t0 + off - 15;
        awm[c][off] = (t >= 0 && t < T_) ? aw[(b*T_ + t)*2 + c] : 0.0f;
    }
    __syncthreads();

    float acc[J_];
    #pragma unroll
    for (int j = 0; j < J_; j++) acc[j] = 0.0f;

    for (int tl = 0; tl < TC; tl++) {
        float w = Wloc[(t0 + tl)*A_ + a];
        #pragma unroll
        for (int k = 0; k < KC_; k++) {
            acc[2*k    ] = fmaf(w, awm[0][tl + k], acc[2*k    ]);
            acc[2*k + 1] = fmaf(w, awm[1][tl + k], acc[2*k + 1]);
        }
    }
    float* dst = &g_Sp[((size_t)(b*NC + ch)*J_)*A_ + a];
    #pragma unroll
    for (int j = 0; j < J_; j++) dst[j*A_] = acc[j];
}

// ---------------- kernel 2b: reduce partials (deterministic) ----------------
__global__ __launch_bounds__(256) void kSr() {
    int idx = blockIdx.x*256 + threadIdx.x;      // B_*J_*A_ = 507904 = 1984*256
    int b  = idx / (J_*A_);
    int ja = idx % (J_*A_);
    float s = 0.0f;
    #pragma unroll
    for (int ch = 0; ch < NC; ch++)
        s += g_Sp[(size_t)(b*NC + ch)*J_*A_ + ja];
    g_S[idx] = s;
}

// -------- kernel 3 (hot): fused v-GEMM + loc-GEMM + score --------
// tile: 64 t-rows x 128 a-cols, 256 threads; micro-tile 8x4 per thread,
// f32x2 packed FMAs (row pairs) in the 512-deep main GEMM.
__global__ __launch_bounds__(256) void kmain(const float* __restrict__ value,
                                             const float* __restrict__ Wm,
                                             const float* __restrict__ Wconv,
                                             const float* __restrict__ Wv) {
    int tile = blockIdx.x;           // 0..15
    int b    = blockIdx.y;           // 0..63
    int t0   = tile * BT;
    int tid  = threadIdx.x;
    int tx   = tid & 31;             // col group (warp lane)
    int ty   = tid >> 5;             // row group (warp id, 8 warps)

    __shared__ __align__(16) float sVal[BK][BT + 2];   // k-major, even stride
    __shared__ __align__(16) float sWm [BK][A_];
    __shared__ __align__(16) float sS  [J_][A_];
    __shared__ float sq[A_];

    // prologue: S tile + q row
    for (int idx = tid; idx < J_*A_; idx += 256)
        sS[idx >> 7][idx & 127] = g_S[(size_t)b*J_*A_ + idx];
    if (tid < A_) sq[tid] = g_q[b*A_ + tid];

    unsigned long long accv[4][4];   // f32x2: rows (ty*8+2ip, +1) x col (tx*4+c)
    #pragma unroll
    for (int i = 0; i < 4; i++)
        #pragma unroll
        for (int c = 0; c < 4; c++) accv[i][c] = 0ull;

    const float* valp = value + ((size_t)b*T_ + t0)*DV_;

    for (int kb = 0; kb < DV_; kb += BK) {
        __syncthreads();
        {   // stage value tile 64x16 (transposed to k-major)
            int row = tid >> 2;
            int c4  = (tid & 3) * 4;
            float4 v4 = *reinterpret_cast<const float4*>(valp + (size_t)row*DV_ + kb + c4);
            sVal[c4+0][row] = v4.x; sVal[c4+1][row] = v4.y;
            sVal[c4+2][row] = v4.z; sVal[c4+3][row] = v4.w;
        }
        {   // stage Wm tile 16x128
            #pragma unroll
            for (int r = 0; r < 8; r++) {
                int idx = tid + r*256;
                int kk = idx >> 7, a = idx & 127;
                sWm[kk][a] = Wm[(size_t)(kb + kk)*A_ + a];
            }
        }
        __syncthreads();

        #pragma unroll
        for (int kk = 0; kk < BK; kk++) {
            unsigned long long a64[4];
            #pragma unroll
            for (int ip = 0; ip < 4; ip++)
                a64[ip] = *reinterpret_cast<const unsigned long long*>(
                              &sVal[kk][ty*8 + 2*ip]);          // warp-broadcast
            float4 bq = *reinterpret_cast<const float4*>(&sWm[kk][tx*4]);
            unsigned long long bd[4];
            asm("mov.b64 %0, {%1,%1};" : "=l"(bd[0]) : "f"(bq.x));
            asm("mov.b64 %0, {%1,%1};" : "=l"(bd[1]) : "f"(bq.y));
            asm("mov.b64 %0, {%1,%1};" : "=l"(bd[2]) : "f"(bq.z));
            asm("mov.b64 %0, {%1,%1};" : "=l"(bd[3]) : "f"(bq.w));
            #pragma unroll
            for (int ip = 0; ip < 4; ip++)
                #pragma unroll
                for (int c = 0; c < 4; c++)
                    asm("fma.rn.f32x2 %0, %1, %2, %0;"
                        : "+l"(accv[ip][c]) : "l"(a64[ip]), "l"(bd[c]));
        }
    }

    // loc GEMM (K=62): loc_pre[t,a] = sum_j Wconv[j*F+t] * S[j,a]
    float accl[8][4];
    #pragma unroll
    for (int i = 0; i < 8; i++)
        #pragma unroll
        for (int c = 0; c < 4; c++) accl[i][c] = 0.0f;

    int frow = t0 + ty*8;
    #pragma unroll 2
    for (int j = 0; j < J_; j++) {
        float4 bq = *reinterpret_cast<const float4*>(&sS[j][tx*4]);
        float a8[8];
        #pragma unroll
        for (int i = 0; i < 8; i++)
            a8[i] = __ldg(&Wconv[(size_t)j*F_ + frow + i]);     // broadcast, L1-hot
        #pragma unroll
        for (int i = 0; i < 8; i++) {
            accl[i][0] = fmaf(a8[i], bq.x, accl[i][0]);
            accl[i][1] = fmaf(a8[i], bq.y, accl[i][1]);
            accl[i][2] = fmaf(a8[i], bq.z, accl[i][2]);
            accl[i][3] = fmaf(a8[i], bq.w, accl[i][3]);
        }
    }

    // epilogue: unpack, tanh, store v, compute score partials, warp-reduce
    float vacc[8][4];
    #pragma unroll
    for (int ip = 0; ip < 4; ip++)
        #pragma unroll
        for (int c = 0; c < 4; c++) {
            unsigned long long u = accv[ip][c];
            vacc[2*ip    ][c] = __uint_as_float((unsigned)(u & 0xffffffffu));
            vacc[2*ip + 1][c] = __uint_as_float((unsigned)(u >> 32));
        }

    float4 wvv = *reinterpret_cast<const float4*>(Wv + tx*4);
    float  qv[4] = { sq[tx*4+0], sq[tx*4+1], sq[tx*4+2], sq[tx*4+3] };

    #pragma unroll
    for (int i = 0; i < 8; i++) {
        int t = t0 + ty*8 + i;
        float vt0 = ftanh(vacc[i][0]);
        float vt1 = ftanh(vacc[i][1]);
        float vt2 = ftanh(vacc[i][2]);
        float vt3 = ftanh(vacc[i][3]);
        float4 vo = make_float4(vt0, vt1, vt2, vt3);
        *reinterpret_cast<float4*>(&g_v[((size_t)b*T_ + t)*A_ + tx*4]) = vo;

        float pe = 0.0f;
        pe = fmaf(ftanh(qv[0] + vt0 + ftanh(accl[i][0])), wvv.x, pe);
        pe = fmaf(ftanh(qv[1] + vt1 + ftanh(accl[i][1])), wvv.y, pe);
        pe = fmaf(ftanh(qv[2] + vt2 + ftanh(accl[i][2])), wvv.z, pe);
        pe = fmaf(ftanh(qv[3] + vt3 + ftanh(accl[i][3])), wvv.w, pe);
        #pragma unroll
        for (int o = 16; o; o >>= 1)
            pe += __shfl_xor_sync(0xffffffffu, pe, o);
        if (tx == 0) g_e[b*T_ + t] = pe;
    }
}

// ---------------- kernel 4: softmax over T + context ----------------
__global__ __launch_bounds__(128) void kctx(float* __restrict__ out) {
    int b = blockIdx.x;
    int tid = threadIdx.x;                // 128
    __shared__ float p[T_];
    __shared__ float red[4];

    float m = -3.0e38f;
    #pragma unroll
    for (int r = 0; r < 8; r++) {
        int t = tid + r*128;
        float e = g_e[b*T_ + t];
        p[t] = e;
        m = fmaxf(m, e);
    }
    #pragma unroll
    for (int o = 16; o; o >>= 1) m = fmaxf(m, __shfl_xor_sync(0xffffffffu, m, o));
    if ((tid & 31) == 0) red[tid >> 5] = m;
    __syncthreads();
    m = fmaxf(fmaxf(red[0], red[1]), fmaxf(red[2], red[3]));
    __syncthreads();

    float s = 0.0f;
    #pragma unroll
    for (int r = 0; r < 8; r++) {
        int t = tid + r*128;
        float ex = __expf(p[t] - m);
        p[t] = ex;
        s += ex;
    }
    #pragma unroll
    for (int o = 16; o; o >>= 1) s += __shfl_xor_sync(0xffffffffu, s, o);
    if ((tid & 31) == 0) red[tid >> 5] = s;
    __syncthreads();
    s = red[0] + red[1] + red[2] + red[3];
    float inv = 1.0f / s;

    // normalized alignment -> out[B*A + b*T + t]
    #pragma unroll
    for (int r = 0; r < 8; r++) {
        int t = tid + r*128;
        float pv = p[t] * inv;
        p[t] = pv;
        out[B_*A_ + b*T_ + t] = pv;
    }
    __syncthreads();

    // context[b,a] = sum_t p[t] * v[b,t,a]
    float acc = 0.0f;
    const float* vp = g_v + (size_t)b*T_*A_ + tid;
    #pragma unroll 8
    for (int t = 0; t < T_; t++)
        acc = fmaf(p[t], vp[(size_t)t*A_], acc);
    out[b*A_ + tid] = acc;
}

// ---------------- launcher ----------------
extern "C" void kernel_launch(void* const* d_in, const int* in_sizes, int n_in,
                              void* d_out, int out_size) {
    const float* query = (const float*)d_in[0];   // [B,1,DQ]
    const float* value = (const float*)d_in[1];   // [B,T,DV]
    const float* awcat = (const float*)d_in[2];   // [B,T,2]
    const float* Wq    = (const float*)d_in[3];   // [DQ,A]
    const float* Wm    = (const float*)d_in[4];   // [DV,A]
    const float* Wv    = (const float*)d_in[5];   // [A,1]
    const float* Wconv = (const float*)d_in[6];   // [K,2,F]
    const float* Wloc  = (const float*)d_in[7];   // [T,A]
    float* out = (float*)d_out;                   // [B*A] context ++ [B*T] alignment

    kq  <<< B_, 128 >>>(query, Wq);
    kS  <<< dim3(B_, NC), 128 >>>(awcat, Wloc);
    kSr <<< (B_*J_*A_)/256, 256 >>>();
    kmain<<< dim3(T_/BT, B_), 256 >>>(value, Wm, Wconv, Wv);
    kctx<<< B_, 128 >>>(out);
}

// round 8
// speedup vs baseline: 1.2108x; 1.2108x over previous
#include <cuda_runtime.h>

#define B_  64
#define T_  1024
#define A_  128
#define F_  1024
#define KC_ 31
#define DQ_ 1024
#define DV_ 512
#define J_  62          // KC_ * 2 channels
#define NC  16          // t-chunks for S partials
#define TC  (T_/NC)     // 64
#define BT  64          // t-tile of main kernel
#define BK  16          // k-tile of main GEMM
#define NKT (DV_/BK)    // 32 k-tiles

// ---- scratch (device globals: no allocation allowed) ----
__device__ float g_v [B_*T_*A_];        // tanh(value @ Wm)
__device__ float g_q [B_*A_];           // tanh(query @ Wq)
__device__ float g_e [B_*T_];           // pre-softmax scores
__device__ float g_S [B_*J_*A_];        // shifted-correlation factor
__device__ float g_Sp[B_*NC*J_*A_];     // deterministic partials for g_S

__device__ __forceinline__ float ftanh(float x) {
    float e = __expf(2.0f * x);
    return 1.0f - __fdividef(2.0f, e + 1.0f);
}

// ---------------- kernel 1: q = tanh(query @ Wq) ----------------
__global__ __launch_bounds__(128) void kq(const float* __restrict__ query,
                                          const float* __restrict__ Wq) {
    int b = blockIdx.x;
    int a = threadIdx.x;
    __shared__ float qs[DQ_];
    for (int d = a; d < DQ_; d += 128) qs[d] = query[b*DQ_ + d];
    __syncthreads();
    float acc = 0.0f;
    #pragma unroll 8
    for (int d = 0; d < DQ_; d++) acc = fmaf(qs[d], Wq[d*A_ + a], acc);
    g_q[b*A_ + a] = ftanh(acc);
}

// ------- kernel 2: S partials. S[b,j=2k+c,a] = sum_t aw[b,t+k-15,c]*Wloc[t,a] -------
__global__ __launch_bounds__(128) void kS(const float* __restrict__ aw,
                                          const float* __restrict__ Wloc) {
    int b  = blockIdx.x;
    int ch = blockIdx.y;
    int a  = threadIdx.x;
    int t0 = ch * TC;

    __shared__ float awm[2][TC + KC_ - 1];
    for (int i = threadIdx.x; i < 2*(TC + KC_ - 1); i += 128) {
        int c = i / (TC + KC_ - 1);
        int off = i % (TC + KC_ - 1);
        int t = t0 + off - 15;
        awm[c][off] = (t >= 0 && t < T_) ? aw[(b*T_ + t)*2 + c] : 0.0f;
    }
    __syncthreads();

    float acc[J_];
    #pragma unroll
    for (int j = 0; j < J_; j++) acc[j] = 0.0f;

    for (int tl = 0; tl < TC; tl++) {
        float w = Wloc[(t0 + tl)*A_ + a];
        #pragma unroll
        for (int k = 0; k < KC_; k++) {
            acc[2*k    ] = fmaf(w, awm[0][tl + k], acc[2*k    ]);
            acc[2*k + 1] = fmaf(w, awm[1][tl + k], acc[2*k + 1]);
        }
    }
    float* dst = &g_Sp[((size_t)(b*NC + ch)*J_)*A_ + a];
    #pragma unroll
    for (int j = 0; j < J_; j++) dst[j*A_] = acc[j];
}

// ---------------- kernel 2b: reduce partials (deterministic) ----------------
__global__ __launch_bounds__(256) void kSr() {
    int idx = blockIdx.x*256 + threadIdx.x;
    int b  = idx / (J_*A_);
    int ja = idx % (J_*A_);
    float s = 0.0f;
    #pragma unroll
    for (int ch = 0; ch < NC; ch++)
        s += g_Sp[(size_t)(b*NC + ch)*J_*A_ + ja];
    g_S[idx] = s;
}

// -------- kernel 3 (hot): fused v-GEMM + loc-GEMM + score --------
// 64x128 tile, 256 thr, 8x4 micro-tile. a-operand pre-duplicated in smem
// (zero dup-movs in the loop), double-buffered staging, 1 sync per k-tile.
__global__ __launch_bounds__(256, 2) void kmain(const float* __restrict__ value,
                                                const float* __restrict__ Wm,
                                                const float* __restrict__ Wconv,
                                                const float* __restrict__ Wv) {
    int tile = blockIdx.x;           // 0..15
    int b    = blockIdx.y;           // 0..63
    int t0   = tile * BT;
    int tid  = threadIdx.x;
    int tx   = tid & 31;             // lane -> 4 cols (tx*4..+3)
    int ty   = tid >> 5;             // warp -> 8 rows (ty*8..+7)

    // duplicated value rows: sValD[kk][2*row] == sValD[kk][2*row+1]
    __shared__ __align__(16) float sValD[2][BK][130];
    __shared__ __align__(16) float sWm  [2][BK][A_];

    const float* valp = value + ((size_t)b*T_ + t0)*DV_;

    int srow = tid >> 2;             // 0..63
    int sk4  = (tid & 3) * 4;        // 0,4,8,12

    unsigned long long accv[8][2];   // [row][colpair]
    #pragma unroll
    for (int r = 0; r < 8; r++) { accv[r][0] = 0ull; accv[r][1] = 0ull; }

    // prologue: prefetch + stage tile 0
    float4 pv  = *reinterpret_cast<const float4*>(valp + (size_t)srow*DV_ + sk4);
    float4 pw0 = *reinterpret_cast<const float4*>(Wm + (size_t)0*A_ + tid*4);
    float4 pw1 = *reinterpret_cast<const float4*>(Wm + (size_t)0*A_ + 1024 + tid*4);
    {
        float2 d;
        d.x = pv.x; d.y = pv.x; *reinterpret_cast<float2*>(&sValD[0][sk4+0][2*srow]) = d;
        d.x = pv.y; d.y = pv.y; *reinterpret_cast<float2*>(&sValD[0][sk4+1][2*srow]) = d;
        d.x = pv.z; d.y = pv.z; *reinterpret_cast<float2*>(&sValD[0][sk4+2][2*srow]) = d;
        d.x = pv.w; d.y = pv.w; *reinterpret_cast<float2*>(&sValD[0][sk4+3][2*srow]) = d;
        *reinterpret_cast<float4*>(&sWm[0][0][0] + tid*4)        = pw0;
        *reinterpret_cast<float4*>(&sWm[0][0][0] + 1024 + tid*4) = pw1;
    }
    __syncthreads();

    #pragma unroll 1
    for (int kt = 0; kt < NKT; kt++) {
        int p = kt & 1;
        bool more = (kt + 1 < NKT);
        if (more) {                  // prefetch next tile (latency hidden by compute)
            int kb = (kt + 1) * BK;
            pv  = *reinterpret_cast<const float4*>(valp + (size_t)srow*DV_ + kb + sk4);
            pw0 = *reinterpret_cast<const float4*>(Wm + (size_t)kb*A_ + tid*4);
            pw1 = *reinterpret_cast<const float4*>(Wm + (size_t)kb*A_ + 1024 + tid*4);
        }

        #pragma unroll
        for (int kk = 0; kk < BK; kk++) {
            ulonglong2 bp = *reinterpret_cast<const ulonglong2*>(&sWm[p][kk][tx*4]);
            #pragma unroll
            for (int r = 0; r < 8; r++) {
                unsigned long long av = *reinterpret_cast<const unsigned long long*>(
                                            &sValD[p][kk][2*(ty*8 + r)]);   // broadcast {v,v}
                asm("fma.rn.f32x2 %0, %1, %2, %0;" : "+l"(accv[r][0]) : "l"(av), "l"(bp.x));
                asm("fma.rn.f32x2 %0, %1, %2, %0;" : "+l"(accv[r][1]) : "l"(av), "l"(bp.y));
            }
        }

        if (more) {
            int q = 1 - p;
            float2 d;
            d.x = pv.x; d.y = pv.x; *reinterpret_cast<float2*>(&sValD[q][sk4+0][2*srow]) = d;
            d.x = pv.y; d.y = pv.y; *reinterpret_cast<float2*>(&sValD[q][sk4+1][2*srow]) = d;
            d.x = pv.z; d.y = pv.z; *reinterpret_cast<float2*>(&sValD[q][sk4+2][2*srow]) = d;
            d.x = pv.w; d.y = pv.w; *reinterpret_cast<float2*>(&sValD[q][sk4+3][2*srow]) = d;
            *reinterpret_cast<float4*>(&sWm[q][0][0] + tid*4)        = pw0;
            *reinterpret_cast<float4*>(&sWm[q][0][0] + 1024 + tid*4) = pw1;
        }
        __syncthreads();
    }

    // loc GEMM (K=62): loc_pre[t,a] = sum_j Wconv[j*F+t] * S[b,j,a]  (S via L2)
    float accl[8][4];
    #pragma unroll
    for (int i = 0; i < 8; i++)
        #pragma unroll
        for (int c = 0; c < 4; c++) accl[i][c] = 0.0f;

    const float4* Sb = reinterpret_cast<const float4*>(g_S + (size_t)b*J_*A_);
    int frow = t0 + ty*8;
    #pragma unroll 2
    for (int j = 0; j < J_; j++) {
        float4 bq = __ldg(Sb + j*32 + tx);
        float a8[8];
        #pragma unroll
        for (int i = 0; i < 8; i++)
            a8[i] = __ldg(&Wconv[(size_t)j*F_ + frow + i]);
        #pragma unroll
        for (int i = 0; i < 8; i++) {
            accl[i][0] = fmaf(a8[i], bq.x, accl[i][0]);
            accl[i][1] = fmaf(a8[i], bq.y, accl[i][1]);
            accl[i][2] = fmaf(a8[i], bq.z, accl[i][2]);
            accl[i][3] = fmaf(a8[i], bq.w, accl[i][3]);
        }
    }

    // epilogue
    float4 wvv = __ldg(reinterpret_cast<const float4*>(Wv) + tx);
    float4 qv4 = __ldg(reinterpret_cast<const float4*>(g_q + b*A_) + tx);
    float qv[4] = { qv4.x, qv4.y, qv4.z, qv4.w };

    #pragma unroll
    for (int i = 0; i < 8; i++) {
        int t = t0 + ty*8 + i;
        unsigned long long u0 = accv[i][0], u1 = accv[i][1];
        float vt0 = ftanh(__uint_as_float((unsigned)(u0 & 0xffffffffu)));
        float vt1 = ftanh(__uint_as_float((unsigned)(u0 >> 32)));
        float vt2 = ftanh(__uint_as_float((unsigned)(u1 & 0xffffffffu)));
        float vt3 = ftanh(__uint_as_float((unsigned)(u1 >> 32)));
        float4 vo = make_float4(vt0, vt1, vt2, vt3);
        *reinterpret_cast<float4*>(&g_v[((size_t)b*T_ + t)*A_ + tx*4]) = vo;

        float pe = 0.0f;
        pe = fmaf(ftanh(qv[0] + vt0 + ftanh(accl[i][0])), wvv.x, pe);
        pe = fmaf(ftanh(qv[1] + vt1 + ftanh(accl[i][1])), wvv.y, pe);
        pe = fmaf(ftanh(qv[2] + vt2 + ftanh(accl[i][2])), wvv.z, pe);
        pe = fmaf(ftanh(qv[3] + vt3 + ftanh(accl[i][3])), wvv.w, pe);
        #pragma unroll
        for (int o = 16; o; o >>= 1)
            pe += __shfl_xor_sync(0xffffffffu, pe, o);
        if (tx == 0) g_e[b*T_ + t] = pe;
    }
}

// ---------------- kernel 4: softmax over T + context (512 thr, 4-way t-split) ----------------
__global__ __launch_bounds__(512) void kctx(float* __restrict__ out) {
    int b = blockIdx.x;
    int tid = threadIdx.x;                // 512
    __shared__ float p[T_];
    __shared__ float red[16];
    __shared__ float cpart[4][A_];

    float e0 = g_e[b*T_ + tid];
    float e1 = g_e[b*T_ + tid + 512];
    float m = fmaxf(e0, e1);
    #pragma unroll
    for (int o = 16; o; o >>= 1) m = fmaxf(m, __shfl_xor_sync(0xffffffffu, m, o));
    if ((tid & 31) == 0) red[tid >> 5] = m;
    __syncthreads();
    if (tid < 32) {
        float mm = (tid < 16) ? red[tid] : -3.0e38f;
        #pragma unroll
        for (int o = 8; o; o >>= 1) mm = fmaxf(mm, __shfl_xor_sync(0xffffffffu, mm, o));
        if (tid == 0) red[0] = mm;
    }
    __syncthreads();
    m = red[0];
    __syncthreads();

    float x0 = __expf(e0 - m);
    float x1 = __expf(e1 - m);
    float s = x0 + x1;
    #pragma unroll
    for (int o = 16; o; o >>= 1) s += __shfl_xor_sync(0xffffffffu, s, o);
    if ((tid & 31) == 0) red[tid >> 5] = s;
    __syncthreads();
    if (tid < 32) {
        float ss = (tid < 16) ? red[tid] : 0.0f;
        #pragma unroll
        for (int o = 8; o; o >>= 1) ss += __shfl_xor_sync(0xffffffffu, ss, o);
        if (tid == 0) red[0] = ss;
    }
    __syncthreads();
    float inv = 1.0f / red[0];

    float p0 = x0 * inv, p1 = x1 * inv;
    p[tid]       = p0;
    p[tid + 512] = p1;
    out[B_*A_ + b*T_ + tid]       = p0;
    out[B_*A_ + b*T_ + tid + 512] = p1;
    __syncthreads();

    // context[b,a] = sum_t p[t] * v[b,t,a], split over 4 t-groups
    int g = tid >> 7;                 // 0..3
    int a = tid & 127;
    const float* vp = g_v + (size_t)b*T_*A_ + (size_t)g*256*A_ + a;
    float acc = 0.0f;
    #pragma unroll 8
    for (int t = 0; t < 256; t++)
        acc = fmaf(p[g*256 + t], vp[(size_t)t*A_], acc);
    cpart[g][a] = acc;
    __syncthreads();
    if (tid < A_)
        out[b*A_ + tid] = cpart[0][tid] + cpart[1][tid] + cpart[2][tid] + cpart[3][tid];
}

// ---------------- launcher ----------------
extern "C" void kernel_launch(void* const* d_in, const int* in_sizes, int n_in,
                              void* d_out, int out_size) {
    const float* query = (const float*)d_in[0];   // [B,1,DQ]
    const float* value = (const float*)d_in[1];   // [B,T,DV]
    const float* awcat = (const float*)d_in[2];   // [B,T,2]
    const float* Wq    = (const float*)d_in[3];   // [DQ,A]
    const float* Wm    = (const float*)d_in[4];   // [DV,A]
    const float* Wv    = (const float*)d_in[5];   // [A,1]
    const float* Wconv = (const float*)d_in[6];   // [K,2,F]
    const float* Wloc  = (const float*)d_in[7];   // [T,A]
    float* out = (float*)d_out;                   // [B*A] context ++ [B*T] alignment

    kq  <<< B_, 128 >>>(query, Wq);
    kS  <<< dim3(B_, NC), 128 >>>(awcat, Wloc);
    kSr <<< (B_*J_*A_)/256, 256 >>>();
    kmain<<< dim3(T_/BT, B_), 256 >>>(value, Wm, Wconv, Wv);
    kctx<<< B_, 512 >>>(out);
}

// round 9
// speedup vs baseline: 1.2310x; 1.0167x over previous
#include <cuda_runtime.h>
#include <cuda_fp16.h>

#define B_  64
#define T_  1024
#define A_  128
#define F_  1024
#define KC_ 31
#define DQ_ 1024
#define DV_ 512
#define J_  62          // KC_ * 2 channels
#define NC  16          // t-chunks for S partials
#define TC  (T_/NC)     // 64
#define BT  64          // t-tile of main kernel
#define BK  16          // k-tile of main GEMM
#define NKT (DV_/BK)    // 32 k-tiles

// ---- scratch (device globals: no allocation allowed) ----
__device__ __half g_vh[B_*T_*A_];       // tanh(value @ Wm), fp16 (context path only)
__device__ float g_q [B_*A_];           // tanh(query @ Wq)
__device__ float g_e [B_*T_];           // pre-softmax scores
__device__ float g_S [B_*J_*A_];        // shifted-correlation factor
__device__ float g_Sp[B_*NC*J_*A_];     // deterministic partials for g_S

__device__ __forceinline__ float ftanh(float x) {
    float e = __expf(2.0f * x);
    return 1.0f - __fdividef(2.0f, e + 1.0f);
}

// ---------------- kernel 1: q = tanh(query @ Wq) ----------------
__global__ __launch_bounds__(128) void kq(const float* __restrict__ query,
                                          const float* __restrict__ Wq) {
    int b = blockIdx.x;
    int a = threadIdx.x;
    __shared__ float qs[DQ_];
    for (int d = a; d < DQ_; d += 128) qs[d] = query[b*DQ_ + d];
    __syncthreads();
    float acc = 0.0f;
    #pragma unroll 8
    for (int d = 0; d < DQ_; d++) acc = fmaf(qs[d], Wq[d*A_ + a], acc);
    g_q[b*A_ + a] = ftanh(acc);
}

// ------- kernel 2: S partials. S[b,j=2k+c,a] = sum_t aw[b,t+k-15,c]*Wloc[t,a] -------
__global__ __launch_bounds__(128) void kS(const float* __restrict__ aw,
                                          const float* __restrict__ Wloc) {
    int b  = blockIdx.x;
    int ch = blockIdx.y;
    int a  = threadIdx.x;
    int t0 = ch * TC;

    __shared__ float awm[2][TC + KC_ - 1];
    for (int i = threadIdx.x; i < 2*(TC + KC_ - 1); i += 128) {
        int c = i / (TC + KC_ - 1);
        int off = i % (TC + KC_ - 1);
        int t = t0 + off - 15;
        awm[c][off] = (t >= 0 && t < T_) ? aw[(b*T_ + t)*2 + c] : 0.0f;
    }
    __syncthreads();

    float acc[J_];
    #pragma unroll
    for (int j = 0; j < J_; j++) acc[j] = 0.0f;

    for (int tl = 0; tl < TC; tl++) {
        float w = Wloc[(t0 + tl)*A_ + a];
        #pragma unroll
        for (int k = 0; k < KC_; k++) {
            acc[2*k    ] = fmaf(w, awm[0][tl + k], acc[2*k    ]);
            acc[2*k + 1] = fmaf(w, awm[1][tl + k], acc[2*k + 1]);
        }
    }
    float* dst = &g_Sp[((size_t)(b*NC + ch)*J_)*A_ + a];
    #pragma unroll
    for (int j = 0; j < J_; j++) dst[j*A_] = acc[j];
}

// ---------------- kernel 2b: reduce partials (deterministic) ----------------
__global__ __launch_bounds__(256) void kSr() {
    int idx = blockIdx.x*256 + threadIdx.x;
    int b  = idx / (J_*A_);
    int ja = idx % (J_*A_);
    float s = 0.0f;
    #pragma unroll
    for (int ch = 0; ch < NC; ch++)
        s += g_Sp[(size_t)(b*NC + ch)*J_*A_ + ja];
    g_S[idx] = s;
}

// -------- kernel 3 (hot): fused v-GEMM + loc-GEMM + score --------
// 64x128 tile, 256 thr, 8x4 micro-tile. a-operand pre-duplicated row-pairs,
// LDS.128 broadcast a-loads (4/kk), double-buffered, 1 sync per k-tile.
__global__ __launch_bounds__(256, 2) void kmain(const float* __restrict__ value,
                                                const float* __restrict__ Wm,
                                                const float* __restrict__ Wconv,
                                                const float* __restrict__ Wv) {
    int tile = blockIdx.x;           // 0..15
    int b    = blockIdx.y;           // 0..63
    int t0   = tile * BT;
    int tid  = threadIdx.x;
    int tx   = tid & 31;             // lane -> 4 cols (tx*4..+3)
    int ty   = tid >> 5;             // warp -> 8 rows (ty*8..+7)

    // duplicated value rows: sValD[kk][2*row] == sValD[kk][2*row+1]; stride 132 (16B-aligned rows)
    __shared__ __align__(16) float sValD[2][BK][132];
    __shared__ __align__(16) float sWm  [2][BK][A_];

    const float* valp = value + ((size_t)b*T_ + t0)*DV_;

    int srow = tid >> 2;             // 0..63
    int sk4  = (tid & 3) * 4;        // 0,4,8,12

    unsigned long long accv[8][2];   // [row][colpair]
    #pragma unroll
    for (int r = 0; r < 8; r++) { accv[r][0] = 0ull; accv[r][1] = 0ull; }

    // prologue: prefetch + stage tile 0
    float4 pv  = *reinterpret_cast<const float4*>(valp + (size_t)srow*DV_ + sk4);
    float4 pw0 = *reinterpret_cast<const float4*>(Wm + (size_t)0*A_ + tid*4);
    float4 pw1 = *reinterpret_cast<const float4*>(Wm + (size_t)0*A_ + 1024 + tid*4);
    {
        float2 d;
        d.x = pv.x; d.y = pv.x; *reinterpret_cast<float2*>(&sValD[0][sk4+0][2*srow]) = d;
        d.x = pv.y; d.y = pv.y; *reinterpret_cast<float2*>(&sValD[0][sk4+1][2*srow]) = d;
        d.x = pv.z; d.y = pv.z; *reinterpret_cast<float2*>(&sValD[0][sk4+2][2*srow]) = d;
        d.x = pv.w; d.y = pv.w; *reinterpret_cast<float2*>(&sValD[0][sk4+3][2*srow]) = d;
        *reinterpret_cast<float4*>(&sWm[0][0][0] + tid*4)        = pw0;
        *reinterpret_cast<float4*>(&sWm[0][0][0] + 1024 + tid*4) = pw1;
    }
    __syncthreads();

    #pragma unroll 1
    for (int kt = 0; kt < NKT; kt++) {
        int p = kt & 1;
        bool more = (kt + 1 < NKT);
        if (more) {                  // prefetch next tile (latency hidden by compute)
            int kb = (kt + 1) * BK;
            pv  = *reinterpret_cast<const float4*>(valp + (size_t)srow*DV_ + kb + sk4);
            pw0 = *reinterpret_cast<const float4*>(Wm + (size_t)kb*A_ + tid*4);
            pw1 = *reinterpret_cast<const float4*>(Wm + (size_t)kb*A_ + 1024 + tid*4);
        }

        #pragma unroll
        for (int kk = 0; kk < BK; kk++) {
            ulonglong2 bp = *reinterpret_cast<const ulonglong2*>(&sWm[p][kk][tx*4]);
            #pragma unroll
            for (int rp = 0; rp < 4; rp++) {
                // one LDS.128 broadcast = row-pair {v,v,v',v'}
                ulonglong2 ap = *reinterpret_cast<const ulonglong2*>(
                                    &sValD[p][kk][4*(ty*4 + rp)]);
                asm("fma.rn.f32x2 %0, %1, %2, %0;" : "+l"(accv[2*rp  ][0]) : "l"(ap.x), "l"(bp.x));
                asm("fma.rn.f32x2 %0, %1, %2, %0;" : "+l"(accv[2*rp  ][1]) : "l"(ap.x), "l"(bp.y));
                asm("fma.rn.f32x2 %0, %1, %2, %0;" : "+l"(accv[2*rp+1][0]) : "l"(ap.y), "l"(bp.x));
                asm("fma.rn.f32x2 %0, %1, %2, %0;" : "+l"(accv[2*rp+1][1]) : "l"(ap.y), "l"(bp.y));
            }
        }

        if (more) {
            int q = 1 - p;
            float2 d;
            d.x = pv.x; d.y = pv.x; *reinterpret_cast<float2*>(&sValD[q][sk4+0][2*srow]) = d;
            d.x = pv.y; d.y = pv.y; *reinterpret_cast<float2*>(&sValD[q][sk4+1][2*srow]) = d;
            d.x = pv.z; d.y = pv.z; *reinterpret_cast<float2*>(&sValD[q][sk4+2][2*srow]) = d;
            d.x = pv.w; d.y = pv.w; *reinterpret_cast<float2*>(&sValD[q][sk4+3][2*srow]) = d;
            *reinterpret_cast<float4*>(&sWm[q][0][0] + tid*4)        = pw0;
            *reinterpret_cast<float4*>(&sWm[q][0][0] + 1024 + tid*4) = pw1;
        }
        __syncthreads();
    }

    // loc GEMM (K=62): loc_pre[t,a] = sum_j Wconv[j*F+t] * S[b,j,a]  (S via L2)
    float accl[8][4];
    #pragma unroll
    for (int i = 0; i < 8; i++)
        #pragma unroll
        for (int c = 0; c < 4; c++) accl[i][c] = 0.0f;

    const float4* Sb = reinterpret_cast<const float4*>(g_S + (size_t)b*J_*A_);
    int frow = t0 + ty*8;
    #pragma unroll 2
    for (int j = 0; j < J_; j++) {
        float4 bq = __ldg(Sb + j*32 + tx);
        float a8[8];
        #pragma unroll
        for (int i = 0; i < 8; i++)
            a8[i] = __ldg(&Wconv[(size_t)j*F_ + frow + i]);
        #pragma unroll
        for (int i = 0; i < 8; i++) {
            accl[i][0] = fmaf(a8[i], bq.x, accl[i][0]);
            accl[i][1] = fmaf(a8[i], bq.y, accl[i][1]);
            accl[i][2] = fmaf(a8[i], bq.z, accl[i][2]);
            accl[i][3] = fmaf(a8[i], bq.w, accl[i][3]);
        }
    }

    // epilogue
    float4 wvv = __ldg(reinterpret_cast<const float4*>(Wv) + tx);
    float4 qv4 = __ldg(reinterpret_cast<const float4*>(g_q + b*A_) + tx);
    float qv[4] = { qv4.x, qv4.y, qv4.z, qv4.w };

    #pragma unroll
    for (int i = 0; i < 8; i++) {
        int t = t0 + ty*8 + i;
        unsigned long long u0 = accv[i][0], u1 = accv[i][1];
        float vt0 = ftanh(__uint_as_float((unsigned)(u0 & 0xffffffffu)));
        float vt1 = ftanh(__uint_as_float((unsigned)(u0 >> 32)));
        float vt2 = ftanh(__uint_as_float((unsigned)(u1 & 0xffffffffu)));
        float vt3 = ftanh(__uint_as_float((unsigned)(u1 >> 32)));

        __half2 h01 = __floats2half2_rn(vt0, vt1);
        __half2 h23 = __floats2half2_rn(vt2, vt3);
        uint2 hv;
        hv.x = *reinterpret_cast<unsigned*>(&h01);
        hv.y = *reinterpret_cast<unsigned*>(&h23);
        *reinterpret_cast<uint2*>(&g_vh[((size_t)b*T_ + t)*A_ + tx*4]) = hv;

        float pe = 0.0f;
        pe = fmaf(ftanh(qv[0] + vt0 + ftanh(accl[i][0])), wvv.x, pe);
        pe = fmaf(ftanh(qv[1] + vt1 + ftanh(accl[i][1])), wvv.y, pe);
        pe = fmaf(ftanh(qv[2] + vt2 + ftanh(accl[i][2])), wvv.z, pe);
        pe = fmaf(ftanh(qv[3] + vt3 + ftanh(accl[i][3])), wvv.w, pe);
        #pragma unroll
        for (int o = 16; o; o >>= 1)
            pe += __shfl_xor_sync(0xffffffffu, pe, o);
        if (tx == 0) g_e[b*T_ + t] = pe;
    }
}

// ------- kernel 4: softmax over T + context (512 thr, 8-way t-split, half2 v) -------
__global__ __launch_bounds__(512) void kctx(float* __restrict__ out) {
    int b = blockIdx.x;
    int tid = threadIdx.x;                // 512
    __shared__ float p[T_];
    __shared__ float red[16];
    __shared__ float cpart[8][A_];

    float e0 = g_e[b*T_ + tid];
    float e1 = g_e[b*T_ + tid + 512];
    float m = fmaxf(e0, e1);
    #pragma unroll
    for (int o = 16; o; o >>= 1) m = fmaxf(m, __shfl_xor_sync(0xffffffffu, m, o));
    if ((tid & 31) == 0) red[tid >> 5] = m;
    __syncthreads();
    if (tid < 32) {
        float mm = (tid < 16) ? red[tid] : -3.0e38f;
        #pragma unroll
        for (int o = 8; o; o >>= 1) mm = fmaxf(mm, __shfl_xor_sync(0xffffffffu, mm, o));
        if (tid == 0) red[0] = mm;
    }
    __syncthreads();
    m = red[0];
    __syncthreads();

    float x0 = __expf(e0 - m);
    float x1 = __expf(e1 - m);
    float s = x0 + x1;
    #pragma unroll
    for (int o = 16; o; o >>= 1) s += __shfl_xor_sync(0xffffffffu, s, o);
    if ((tid & 31) == 0) red[tid >> 5] = s;
    __syncthreads();
    if (tid < 32) {
        float ss = (tid < 16) ? red[tid] : 0.0f;
        #pragma unroll
        for (int o = 8; o; o >>= 1) ss += __shfl_xor_sync(0xffffffffu, ss, o);
        if (tid == 0) red[0] = ss;
    }
    __syncthreads();
    float inv = 1.0f / red[0];

    float p0 = x0 * inv, p1 = x1 * inv;
    p[tid]       = p0;
    p[tid + 512] = p1;
    out[B_*A_ + b*T_ + tid]       = p0;
    out[B_*A_ + b*T_ + tid + 512] = p1;
    __syncthreads();

    // context[b,a] = sum_t p[t] * v[b,t,a]; 8 t-groups x 64 half2 columns
    int g  = tid >> 6;                // 0..7
    int a2 = tid & 63;                // half2 column
    const __half2* vp = reinterpret_cast<const __half2*>(g_vh)
                        + ((size_t)b*T_ + (size_t)g*128)*64 + a2;
    float accx = 0.0f, accy = 0.0f;
    #pragma unroll 8
    for (int t = 0; t < 128; t++) {
        float2 vv = __half22float2(vp[(size_t)t*64]);
        float pt = p[g*128 + t];
        accx = fmaf(pt, vv.x, accx);
        accy = fmaf(pt, vv.y, accy);
    }
    cpart[g][2*a2]     = accx;
    cpart[g][2*a2 + 1] = accy;
    __syncthreads();
    if (tid < A_) {
        float c = 0.0f;
        #pragma unroll
        for (int gg = 0; gg < 8; gg++) c += cpart[gg][tid];
        out[b*A_ + tid] = c;
    }
}

// ---------------- launcher ----------------
extern "C" void kernel_launch(void* const* d_in, const int* in_sizes, int n_in,
                              void* d_out, int out_size) {
    const float* query = (const float*)d_in[0];   // [B,1,DQ]
    const float* value = (const float*)d_in[1];   // [B,T,DV]
    const float* awcat = (const float*)d_in[2];   // [B,T,2]
    const float* Wq    = (const float*)d_in[3];   // [DQ,A]
    const float* Wm    = (const float*)d_in[4];   // [DV,A]
    const float* Wv    = (const float*)d_in[5];   // [A,1]
    const float* Wconv = (const float*)d_in[6];   // [K,2,F]
    const float* Wloc  = (const float*)d_in[7];   // [T,A]
    float* out = (float*)d_out;                   // [B*A] context ++ [B*T] alignment

    kq  <<< B_, 128 >>>(query, Wq);
    kS  <<< dim3(B_, NC), 128 >>>(awcat, Wloc);
    kSr <<< (B_*J_*A_)/256, 256 >>>();
    kmain<<< dim3(T_/BT, B_), 256 >>>(value, Wm, Wconv, Wv);
    kctx<<< B_, 512 >>>(out);
}

// round 11
// speedup vs baseline: 1.6969x; 1.3785x over previous
#include <cuda_runtime.h>
#include <cuda_fp16.h>
#include <cuda_bf16.h>
#include <cstdint>

#define B_  64
#define T_  1024
#define A_  128
#define F_  1024
#define KC_ 31
#define DQ_ 1024
#define DV_ 512
#define J_  62
#define NC  16
#define TC  (T_/NC)     // 64
#define NTT 8           // t-tiles of 128
#define NCH 8           // k-chunks of 64
#define CHK 8192        // elems per bf16 image chunk (128 x 64)

// ---- scratch (device globals) ----
__device__ __half g_vh[B_*T_*A_];
__device__ float g_q [B_*A_];
__device__ float g_e [B_*T_];
__device__ float g_S [B_*J_*A_];
__device__ float g_Sp[B_*NC*J_*A_];
// bf16 hi/lo images, plain row-major [row][64 k]
__device__ __align__(16) __nv_bfloat16 gBimg[2][NCH][CHK];  // Wm^T   (row=a)
__device__ __align__(16) __nv_bfloat16 gCimg[2][NTT][CHK];  // Wconv^T(row=t_local)
__device__ __align__(16) __nv_bfloat16 gSimg[2][B_ ][CHK];  // S^T    (row=a)

__device__ __forceinline__ float ftanh(float x) {
    float e = __expf(2.0f * x);
    return 1.0f - __fdividef(2.0f, e + 1.0f);
}

__device__ __forceinline__ void split8(const float* x, uint4& hi, uint4& lo) {
    unsigned hw[4], lw[4];
    #pragma unroll
    for (int p = 0; p < 4; p++) {
        __nv_bfloat162 h = __floats2bfloat162_rn(x[2*p], x[2*p+1]);
        float r0 = x[2*p]   - __low2float(h);
        float r1 = x[2*p+1] - __high2float(h);
        __nv_bfloat162 l = __floats2bfloat162_rn(r0, r1);
        hw[p] = *reinterpret_cast<unsigned*>(&h);
        lw[p] = *reinterpret_cast<unsigned*>(&l);
    }
    hi = make_uint4(hw[0], hw[1], hw[2], hw[3]);
    lo = make_uint4(lw[0], lw[1], lw[2], lw[3]);
}

#define CP16(dst_u32, src_ptr) \
    asm volatile("cp.async.ca.shared.global [%0], [%1], 16;" \
                 :: "r"(dst_u32), "l"(src_ptr) : "memory")
#define CP_COMMIT() asm volatile("cp.async.commit_group;" ::: "memory")
#define CP_WAIT0()  asm volatile("cp.async.wait_group 0;" ::: "memory")

__device__ __forceinline__ void mma4(float* c, const uint32_t* a,
                                     uint32_t b0, uint32_t b1) {
    asm volatile(
        "mma.sync.aligned.m16n8k16.row.col.f32.bf16.bf16.f32 "
        "{%0,%1,%2,%3},{%4,%5,%6,%7},{%8,%9},{%0,%1,%2,%3};"
        : "+f"(c[0]), "+f"(c[1]), "+f"(c[2]), "+f"(c[3])
        : "r"(a[0]), "r"(a[1]), "r"(a[2]), "r"(a[3]), "r"(b0), "r"(b1));
}

// ---------------- kernel 1: q = tanh(query @ Wq) ----------------
__global__ __launch_bounds__(128) void kq(const float* __restrict__ query,
                                          const float* __restrict__ Wq) {
    int b = blockIdx.x;
    int a = threadIdx.x;
    __shared__ float qs[DQ_];
    for (int d = a; d < DQ_; d += 128) qs[d] = query[b*DQ_ + d];
    __syncthreads();
    float acc = 0.0f;
    #pragma unroll 8
    for (int d = 0; d < DQ_; d++) acc = fmaf(qs[d], Wq[d*A_ + a], acc);
    g_q[b*A_ + a] = ftanh(acc);
}

// ------- kernel 2: S partials -------
__global__ __launch_bounds__(128) void kS(const float* __restrict__ aw,
                                          const float* __restrict__ Wloc) {
    int b  = blockIdx.x;
    int ch = blockIdx.y;
    int a  = threadIdx.x;
    int t0 = ch * TC;

    __shared__ float awm[2][TC + KC_ - 1];
    for (int i = threadIdx.x; i < 2*(TC + KC_ - 1); i += 128) {
        int c = i / (TC + KC_ - 1);
        int off = i % (TC + KC_ - 1);
        int t = t0 + off - 15;
        awm[c][off] = (t >= 0 && t < T_) ? aw[(b*T_ + t)*2 + c] : 0.0f;
    }
    __syncthreads();

    float acc[J_];
    #pragma unroll
    for (int j = 0; j < J_; j++) acc[j] = 0.0f;
    for (int tl = 0; tl < TC; tl++) {
        float w = Wloc[(t0 + tl)*A_ + a];
        #pragma unroll
        for (int k = 0; k < KC_; k++) {
            acc[2*k    ] = fmaf(w, awm[0][tl + k], acc[2*k    ]);
            acc[2*k + 1] = fmaf(w, awm[1][tl + k], acc[2*k + 1]);
        }
    }
    float* dst = &g_Sp[((size_t)(b*NC + ch)*J_)*A_ + a];
    #pragma unroll
    for (int j = 0; j < J_; j++) dst[j*A_] = acc[j];
}

// ---------------- kernel 2b: reduce partials ----------------
__global__ __launch_bounds__(256) void kSr() {
    int idx = blockIdx.x*256 + threadIdx.x;
    int b  = idx / (J_*A_);
    int ja = idx % (J_*A_);
    float s = 0.0f;
    #pragma unroll
    for (int ch = 0; ch < NC; ch++)
        s += g_Sp[(size_t)(b*NC + ch)*J_*A_ + ja];
    g_S[idx] = s;
}

// -------- prep kernels: plain row-major bf16 hi/lo chunk images --------
__global__ __launch_bounds__(128) void kprepB(const float* __restrict__ Wm) {
    int c = blockIdx.x;
    int a = threadIdx.x;
    #pragma unroll 1
    for (int k8 = 0; k8 < 8; k8++) {
        float x[8];
        #pragma unroll
        for (int i = 0; i < 8; i++)
            x[i] = Wm[(size_t)(c*64 + k8*8 + i)*A_ + a];
        uint4 hi, lo;
        split8(x, hi, lo);
        *reinterpret_cast<uint4*>(&gBimg[0][c][a*64 + k8*8]) = hi;
        *reinterpret_cast<uint4*>(&gBimg[1][c][a*64 + k8*8]) = lo;
    }
}
__global__ __launch_bounds__(128) void kprepC(const float* __restrict__ Wconv) {
    int tt = blockIdx.x;
    int t  = threadIdx.x;
    #pragma unroll 1
    for (int k8 = 0; k8 < 8; k8++) {
        float x[8];
        #pragma unroll
        for (int i = 0; i < 8; i++) {
            int j = k8*8 + i;
            x[i] = (j < J_) ? Wconv[(size_t)j*F_ + tt*128 + t] : 0.0f;
        }
        uint4 hi, lo;
        split8(x, hi, lo);
        *reinterpret_cast<uint4*>(&gCimg[0][tt][t*64 + k8*8]) = hi;
        *reinterpret_cast<uint4*>(&gCimg[1][tt][t*64 + k8*8]) = lo;
    }
}
__global__ __launch_bounds__(128) void kprepS() {
    int b = blockIdx.x;
    int a = threadIdx.x;
    #pragma unroll 1
    for (int k8 = 0; k8 < 8; k8++) {
        float x[8];
        #pragma unroll
        for (int i = 0; i < 8; i++) {
            int j = k8*8 + i;
            x[i] = (j < J_) ? g_S[((size_t)b*J_ + j)*A_ + a] : 0.0f;
        }
        uint4 hi, lo;
        split8(x, hi, lo);
        *reinterpret_cast<uint4*>(&gSimg[0][b][a*64 + k8*8]) = hi;
        *reinterpret_cast<uint4*>(&gSimg[1][b][a*64 + k8*8]) = lo;
    }
}

// -------- kernel 3 (hot): mma.sync bf16 3-split v-GEMM + loc-GEMM --------
#define SROW   144                      // smem row stride bytes (64 bf16 + pad)
#define TILE_B (128*SROW)               // 18432
#define OFF_A(buf,part) ((uint32_t)(((buf)*2+(part))*TILE_B))
#define OFF_B(buf,part) ((uint32_t)(73728u + ((buf)*2+(part))*TILE_B))
#define OFF_EP 147456u
#define OFF_Q  149504u
#define OFF_WV 150016u
#define SMEM_DYN 150528

__global__ __launch_bounds__(256) void kmain(const float* __restrict__ value,
                                             const float* __restrict__ Wv) {
    extern __shared__ __align__(16) char sm[];
    uint32_t smu = (uint32_t)__cvta_generic_to_shared(sm);

    int tt  = blockIdx.x;            // 0..7
    int b   = blockIdx.y;            // 0..63
    int t0  = tt * 128;
    int tid = threadIdx.x;
    int lane = tid & 31;
    int wid  = tid >> 5;             // 0..7
    int wr   = wid >> 2;             // 0..1 row-group (64 t-rows each)
    int wc   = wid & 3;              // 0..3 col-group (32 a-cols each)
    int grp  = lane >> 2;            // 0..7
    int tig  = lane & 3;             // 0..3

    float* sq    = reinterpret_cast<float*>(sm + OFF_Q);
    float* sWv   = reinterpret_cast<float*>(sm + OFF_WV);
    float* epart = reinterpret_cast<float*>(sm + OFF_EP);   // [128][4]

    if (tid < 128) { sq[tid] = g_q[b*A_ + tid]; sWv[tid] = Wv[tid]; }

    // prologue: stage chunk 0 (loc: A=Wconv^T tile, B=S^T tile) into buf0
    #pragma unroll
    for (int part = 0; part < 2; part++)
        #pragma unroll
        for (int r = 0; r < 4; r++) {
            int i = tid + r*256;
            int row = i >> 3, cc = i & 7;
            uint32_t doff = (uint32_t)(row*SROW + cc*16);
            CP16(smu + OFF_A(0, part) + doff, (const char*)&gCimg[part][tt][i*8]);
            CP16(smu + OFF_B(0, part) + doff, (const char*)&gSimg[part][b][i*8]);
        }
    CP_COMMIT();
    CP_WAIT0();
    __syncthreads();

    float accv[4][4][4];             // [mt][nt][frag]
    float accl[4][4][4];
    #pragma unroll
    for (int mt = 0; mt < 4; mt++)
        #pragma unroll
        for (int nt = 0; nt < 4; nt++)
            #pragma unroll
            for (int f = 0; f < 4; f++) { accv[mt][nt][f] = 0.f; accl[mt][nt][f] = 0.f; }

    int vrow = tid >> 1;             // conversion row 0..127
    int vkh  = tid & 1;              // k-half
    const float* vbase = value + ((size_t)(b*T_) + t0 + vrow)*DV_ + vkh*32;

    auto compute_chunk = [&](float (&acc)[4][4][4], int pb) {
        uint32_t aH = OFF_A(pb, 0), aL = OFF_A(pb, 1);
        uint32_t bH = OFF_B(pb, 0), bL = OFF_B(pb, 1);
        #pragma unroll
        for (int kk = 0; kk < 4; kk++) {
            uint32_t Ah[4][4], Al[4][4];
            #pragma unroll
            for (int mt = 0; mt < 4; mt++)
                #pragma unroll
                for (int rg = 0; rg < 4; rg++) {
                    int row = wr*64 + mt*16 + grp + (rg & 1)*8;
                    int col = kk*16 + 2*tig + (rg >> 1)*8;
                    uint32_t off = (uint32_t)(row*SROW + col*2);
                    Ah[mt][rg] = *reinterpret_cast<const uint32_t*>(sm + aH + off);
                    Al[mt][rg] = *reinterpret_cast<const uint32_t*>(sm + aL + off);
                }
            #pragma unroll
            for (int nt = 0; nt < 4; nt++) {
                int nrow = wc*32 + nt*8 + grp;
                uint32_t off0 = (uint32_t)(nrow*SROW + (kk*16 + 2*tig)*2);
                uint32_t Bh0 = *reinterpret_cast<const uint32_t*>(sm + bH + off0);
                uint32_t Bh1 = *reinterpret_cast<const uint32_t*>(sm + bH + off0 + 16);
                uint32_t Bl0 = *reinterpret_cast<const uint32_t*>(sm + bL + off0);
                uint32_t Bl1 = *reinterpret_cast<const uint32_t*>(sm + bL + off0 + 16);
                #pragma unroll
                for (int mt = 0; mt < 4; mt++) {
                    mma4(acc[mt][nt], Ah[mt], Bh0, Bh1);   // hi*hi
                    mma4(acc[mt][nt], Al[mt], Bh0, Bh1);   // lo*hi
                    mma4(acc[mt][nt], Ah[mt], Bl0, Bl1);   // hi*lo
                }
            }
        }
    };

    #pragma unroll 1
    for (int q = 0; q < 9; q++) {
        int pb = q & 1;
        int nb = (q + 1) & 1;
        float4 vf[8];
        if (q < 8) {
            // stage B chunk q (Wm^T hi/lo) via cp.async
            #pragma unroll
            for (int part = 0; part < 2; part++)
                #pragma unroll
                for (int r = 0; r < 4; r++) {
                    int i = tid + r*256;
                    int row = i >> 3, cc = i & 7;
                    CP16(smu + OFF_B(nb, part) + (uint32_t)(row*SROW + cc*16),
                         (const char*)&gBimg[part][q][i*8]);
                }
            CP_COMMIT();
            // issue value LDGs (k-chunk q); consumed after compute
            const float* src = vbase + q*64;
            #pragma unroll
            for (int g = 0; g < 8; g++)
                vf[g] = *reinterpret_cast<const float4*>(src + g*4);
        }

        if (q == 0) compute_chunk(accl, pb);
        else        compute_chunk(accv, pb);

        if (q < 8) {
            // convert staged value rows -> bf16 hi/lo into A buffers
            char* dH = sm + OFF_A(nb, 0) + vrow*SROW + vkh*64;
            char* dL = sm + OFF_A(nb, 1) + vrow*SROW + vkh*64;
            #pragma unroll
            for (int g = 0; g < 4; g++) {
                float x[8];
                x[0] = vf[2*g].x;   x[1] = vf[2*g].y;
                x[2] = vf[2*g].z;   x[3] = vf[2*g].w;
                x[4] = vf[2*g+1].x; x[5] = vf[2*g+1].y;
                x[6] = vf[2*g+1].z; x[7] = vf[2*g+1].w;
                uint4 hi, lo;
                split8(x, hi, lo);
                *reinterpret_cast<uint4*>(dH + g*16) = hi;
                *reinterpret_cast<uint4*>(dL + g*16) = lo;
            }
        }
        CP_WAIT0();
        __syncthreads();
    }

    // ---- epilogue ----
    float qc[8], wv[8];
    #pragma unroll
    for (int nt = 0; nt < 4; nt++) {
        int c0 = wc*32 + nt*8 + 2*tig;
        qc[nt*2]   = sq[c0];     qc[nt*2+1] = sq[c0+1];
        wv[nt*2]   = sWv[c0];    wv[nt*2+1] = sWv[c0+1];
    }

    #pragma unroll
    for (int mt = 0; mt < 4; mt++) {
        #pragma unroll
        for (int h = 0; h < 2; h++) {
            int row = wr*64 + mt*16 + grp + h*8;
            int t = t0 + row;
            float pe = 0.0f;
            #pragma unroll
            for (int nt = 0; nt < 4; nt++) {
                float v0 = ftanh(accv[mt][nt][h*2 + 0]);
                float v1 = ftanh(accv[mt][nt][h*2 + 1]);
                float l0 = ftanh(accl[mt][nt][h*2 + 0]);
                float l1 = ftanh(accl[mt][nt][h*2 + 1]);
                int c0 = wc*32 + nt*8 + 2*tig;
                __half2 hv = __floats2half2_rn(v0, v1);
                *reinterpret_cast<__half2*>(&g_vh[((size_t)b*T_ + t)*A_ + c0]) = hv;
                pe += ftanh(qc[nt*2]   + v0 + l0) * wv[nt*2];
                pe += ftanh(qc[nt*2+1] + v1 + l1) * wv[nt*2+1];
            }
            pe += __shfl_xor_sync(0xffffffffu, pe, 1);
            pe += __shfl_xor_sync(0xffffffffu, pe, 2);
            if (tig == 0) epart[row*4 + wc] = pe;
        }
    }
    __syncthreads();
    if (tid < 128) {
        float e = epart[tid*4+0] + epart[tid*4+1] + epart[tid*4+2] + epart[tid*4+3];
        g_e[b*T_ + t0 + tid] = e;
    }
}

// ------- kernel 4: softmax over T + context (512 thr, half2 v) -------
__global__ __launch_bounds__(512) void kctx(float* __restrict__ out) {
    int b = blockIdx.x;
    int tid = threadIdx.x;
    __shared__ float p[T_];
    __shared__ float red[16];
    __shared__ float cpart[8][A_];

    float e0 = g_e[b*T_ + tid];
    float e1 = g_e[b*T_ + tid + 512];
    float m = fmaxf(e0, e1);
    #pragma unroll
    for (int o = 16; o; o >>= 1) m = fmaxf(m, __shfl_xor_sync(0xffffffffu, m, o));
    if ((tid & 31) == 0) red[tid >> 5] = m;
    __syncthreads();
    if (tid < 32) {
        float mm = (tid < 16) ? red[tid] : -3.0e38f;
        #pragma unroll
        for (int o = 8; o; o >>= 1) mm = fmaxf(mm, __shfl_xor_sync(0xffffffffu, mm, o));
        if (tid == 0) red[0] = mm;
    }
    __syncthreads();
    m = red[0];
    __syncthreads();

    float x0 = __expf(e0 - m);
    float x1 = __expf(e1 - m);
    float s = x0 + x1;
    #pragma unroll
    for (int o = 16; o; o >>= 1) s += __shfl_xor_sync(0xffffffffu, s, o);
    if ((tid & 31) == 0) red[tid >> 5] = s;
    __syncthreads();
    if (tid < 32) {
        float ss = (tid < 16) ? red[tid] : 0.0f;
        #pragma unroll
        for (int o = 8; o; o >>= 1) ss += __shfl_xor_sync(0xffffffffu, ss, o);
        if (tid == 0) red[0] = ss;
    }
    __syncthreads();
    float inv = 1.0f / red[0];

    float p0 = x0 * inv, p1 = x1 * inv;
    p[tid]       = p0;
    p[tid + 512] = p1;
    out[B_*A_ + b*T_ + tid]       = p0;
    out[B_*A_ + b*T_ + tid + 512] = p1;
    __syncthreads();

    int g  = tid >> 6;
    int a2 = tid & 63;
    const __half2* vp = reinterpret_cast<const __half2*>(g_vh)
                        + ((size_t)b*T_ + (size_t)g*128)*64 + a2;
    float accx = 0.0f, accy = 0.0f;
    #pragma unroll 8
    for (int t = 0; t < 128; t++) {
        float2 vv = __half22float2(vp[(size_t)t*64]);
        float pt = p[g*128 + t];
        accx = fmaf(pt, vv.x, accx);
        accy = fmaf(pt, vv.y, accy);
    }
    cpart[g][2*a2]     = accx;
    cpart[g][2*a2 + 1] = accy;
    __syncthreads();
    if (tid < A_) {
        float c = 0.0f;
        #pragma unroll
        for (int gg = 0; gg < 8; gg++) c += cpart[gg][tid];
        out[b*A_ + tid] = c;
    }
}

// ---------------- launcher ----------------
extern "C" void kernel_launch(void* const* d_in, const int* in_sizes, int n_in,
                              void* d_out, int out_size) {
    const float* query = (const float*)d_in[0];
    const float* value = (const float*)d_in[1];
    const float* awcat = (const float*)d_in[2];
    const float* Wq    = (const float*)d_in[3];
    const float* Wm    = (const float*)d_in[4];
    const float* Wv    = (const float*)d_in[5];
    const float* Wconv = (const float*)d_in[6];
    const float* Wloc  = (const float*)d_in[7];
    float* out = (float*)d_out;

    static bool attr_set = false;
    if (!attr_set) {
        cudaFuncSetAttribute(kmain, cudaFuncAttributeMaxDynamicSharedMemorySize, SMEM_DYN);
        attr_set = true;
    }

    kq    <<< B_, 128 >>>(query, Wq);
    kprepB<<< NCH, 128 >>>(Wm);
    kprepC<<< NTT, 128 >>>(Wconv);
    kS    <<< dim3(B_, NC), 128 >>>(awcat, Wloc);
    kSr   <<< (B_*J_*A_)/256, 256 >>>();
    kprepS<<< B_, 128 >>>();
    kmain <<< dim3(NTT, B_), 256, SMEM_DYN >>>(value, Wv);
    kctx  <<< B_, 512 >>>(out);
}

// round 12
// speedup vs baseline: 1.9993x; 1.1782x over previous
#include <cuda_runtime.h>
#include <cuda_fp16.h>
#include <cuda_bf16.h>
#include <cstdint>

#define B_  64
#define T_  1024
#define A_  128
#define F_  1024
#define KC_ 31
#define DQ_ 1024
#define DV_ 512
#define J_  62
#define NCS 8           // kS t-chunks
#define TCS 128         // t per chunk
#define NTT 8           // t-tiles of 128
#define NCH 8           // k-chunks of 64
#define CHK 8192        // elems per bf16 image chunk (128 x 64)

// ---- scratch (device globals) ----
__device__ __half g_vh[B_*T_*A_];
__device__ float g_q [B_*A_];
__device__ float g_qp[256*A_];          // kq partials (b*4+quarter)
__device__ float g_e [B_*T_];
__device__ float g_Sp[B_*NCS*J_*A_];    // S partials (16 MB)
// bf16 hi/lo images, plain row-major [row][64 k]
__device__ __align__(16) __nv_bfloat16 gBimg[2][NCH][CHK];  // Wm^T   (row=a)
__device__ __align__(16) __nv_bfloat16 gCimg[2][NTT][CHK];  // Wconv^T(row=t_local)
__device__ __align__(16) __nv_bfloat16 gSimg[2][B_ ][CHK];  // S^T    (row=a)

__device__ __forceinline__ float ftanh(float x) {
    float e = __expf(2.0f * x);
    return 1.0f - __fdividef(2.0f, e + 1.0f);
}

__device__ __forceinline__ void split8(const float* x, uint4& hi, uint4& lo) {
    unsigned hw[4], lw[4];
    #pragma unroll
    for (int p = 0; p < 4; p++) {
        __nv_bfloat162 h = __floats2bfloat162_rn(x[2*p], x[2*p+1]);
        float r0 = x[2*p]   - __low2float(h);
        float r1 = x[2*p+1] - __high2float(h);
        __nv_bfloat162 l = __floats2bfloat162_rn(r0, r1);
        hw[p] = *reinterpret_cast<unsigned*>(&h);
        lw[p] = *reinterpret_cast<unsigned*>(&l);
    }
    hi = make_uint4(hw[0], hw[1], hw[2], hw[3]);
    lo = make_uint4(lw[0], lw[1], lw[2], lw[3]);
}

#define CP16(dst_u32, src_ptr) \
    asm volatile("cp.async.ca.shared.global [%0], [%1], 16;" \
                 :: "r"(dst_u32), "l"(src_ptr) : "memory")
#define CP_COMMIT() asm volatile("cp.async.commit_group;" ::: "memory")
#define CP_WAIT0()  asm volatile("cp.async.wait_group 0;" ::: "memory")

__device__ __forceinline__ void mma4(float* c, const uint32_t* a,
                                     uint32_t b0, uint32_t b1) {
    asm volatile(
        "mma.sync.aligned.m16n8k16.row.col.f32.bf16.bf16.f32 "
        "{%0,%1,%2,%3},{%4,%5,%6,%7},{%8,%9},{%0,%1,%2,%3};"
        : "+f"(c[0]), "+f"(c[1]), "+f"(c[2]), "+f"(c[3])
        : "r"(a[0]), "r"(a[1]), "r"(a[2]), "r"(a[3]), "r"(b0), "r"(b1));
}

// =============== stage 1: kq-partials | prepB | prepC | kS (fused) ===============
// blocks [0,256):   kq partial   (b = blk>>2, quarter = blk&3)
// blocks [256,264): prepB        (c = blk-256)
// blocks [264,272): prepC        (tt = blk-264)
// blocks [272,784): kS           (i = blk-272: b = i>>3, ch = i&7)
#define S1_KQ   256
#define S1_PB   (S1_KQ + NCH)
#define S1_PC   (S1_PB + NTT)
#define S1_TOT  (S1_PC + B_*NCS)

__global__ __launch_bounds__(128) void kstage1(const float* __restrict__ query,
                                               const float* __restrict__ Wq,
                                               const float* __restrict__ Wm,
                                               const float* __restrict__ Wconv,
                                               const float* __restrict__ aw,
                                               const float* __restrict__ Wloc) {
    int blk = blockIdx.x;
    int tid = threadIdx.x;

    if (blk < S1_KQ) {                     // ---- kq partial ----
        int b = blk >> 2, qq = blk & 3;
        __shared__ float qs[256];
        qs[tid]       = query[b*DQ_ + qq*256 + tid];
        qs[tid + 128] = query[b*DQ_ + qq*256 + 128 + tid];
        __syncthreads();
        float acc = 0.0f;
        #pragma unroll 8
        for (int d = 0; d < 256; d++)
            acc = fmaf(qs[d], Wq[(size_t)(qq*256 + d)*A_ + tid], acc);
        g_qp[blk*A_ + tid] = acc;
    } else if (blk < S1_PB) {              // ---- prepB: Wm^T bf16 hi/lo ----
        int c = blk - S1_KQ;
        #pragma unroll 1
        for (int k8 = 0; k8 < 8; k8++) {
            float x[8];
            #pragma unroll
            for (int i = 0; i < 8; i++)
                x[i] = Wm[(size_t)(c*64 + k8*8 + i)*A_ + tid];
            uint4 hi, lo;
            split8(x, hi, lo);
            *reinterpret_cast<uint4*>(&gBimg[0][c][tid*64 + k8*8]) = hi;
            *reinterpret_cast<uint4*>(&gBimg[1][c][tid*64 + k8*8]) = lo;
        }
    } else if (blk < S1_PC) {              // ---- prepC: Wconv^T bf16 hi/lo ----
        int tt = blk - S1_PB;
        #pragma unroll 1
        for (int k8 = 0; k8 < 8; k8++) {
            float x[8];
            #pragma unroll
            for (int i = 0; i < 8; i++) {
                int j = k8*8 + i;
                x[i] = (j < J_) ? Wconv[(size_t)j*F_ + tt*128 + tid] : 0.0f;
            }
            uint4 hi, lo;
            split8(x, hi, lo);
            *reinterpret_cast<uint4*>(&gCimg[0][tt][tid*64 + k8*8]) = hi;
            *reinterpret_cast<uint4*>(&gCimg[1][tt][tid*64 + k8*8]) = lo;
        }
    } else {                               // ---- kS: f32x2 shifted-corr partials ----
        int i  = blk - S1_PC;
        int b  = i >> 3;
        int ch = i & 7;
        int t0 = ch * TCS;

        __shared__ float2 awm2[TCS + KC_ - 1];   // interleaved channels
        for (int idx = tid; idx < TCS + KC_ - 1; idx += 128) {
            int t = t0 + idx - 15;
            float2 v = make_float2(0.0f, 0.0f);
            if (t >= 0 && t < T_) {
                v.x = aw[(b*T_ + t)*2 + 0];
                v.y = aw[(b*T_ + t)*2 + 1];
            }
            awm2[idx] = v;
        }
        __syncthreads();

        unsigned long long acc2[KC_];
        #pragma unroll
        for (int k = 0; k < KC_; k++) acc2[k] = 0ull;

        #pragma unroll 1
        for (int tl = 0; tl < TCS; tl++) {
            float w = Wloc[(size_t)(t0 + tl)*A_ + tid];
            unsigned long long wd;
            asm("mov.b64 %0, {%1,%1};" : "=l"(wd) : "f"(w));
            #pragma unroll
            for (int k = 0; k < KC_; k++) {
                unsigned long long bv = *reinterpret_cast<const unsigned long long*>(&awm2[tl + k]);
                asm("fma.rn.f32x2 %0, %1, %2, %0;" : "+l"(acc2[k]) : "l"(wd), "l"(bv));
            }
        }
        float* dst = &g_Sp[((size_t)(b*NCS + ch)*J_)*A_ + tid];
        #pragma unroll
        for (int k = 0; k < KC_; k++) {
            dst[(2*k    )*A_] = __uint_as_float((unsigned)(acc2[k] & 0xffffffffu));
            dst[(2*k + 1)*A_] = __uint_as_float((unsigned)(acc2[k] >> 32));
        }
    }
}

// =============== stage 2: finalize q + reduce S -> bf16 images ===============
__global__ __launch_bounds__(128) void kstage2() {
    int b = blockIdx.x;
    int a = threadIdx.x;

    float qa = g_qp[(b*4+0)*A_ + a] + g_qp[(b*4+1)*A_ + a]
             + g_qp[(b*4+2)*A_ + a] + g_qp[(b*4+3)*A_ + a];
    g_q[b*A_ + a] = ftanh(qa);

    const float* part = &g_Sp[(size_t)(b*NCS)*J_*A_ + a];
    #pragma unroll 1
    for (int j8 = 0; j8 < 8; j8++) {
        float x[8];
        #pragma unroll
        for (int i = 0; i < 8; i++) {
            int j = j8*8 + i;
            float s = 0.0f;
            if (j < J_) {
                #pragma unroll
                for (int ch = 0; ch < NCS; ch++)
                    s += part[((size_t)ch*J_ + j)*A_];
            }
            x[i] = s;
        }
        uint4 hi, lo;
        split8(x, hi, lo);
        *reinterpret_cast<uint4*>(&gSimg[0][b][a*64 + j8*8]) = hi;
        *reinterpret_cast<uint4*>(&gSimg[1][b][a*64 + j8*8]) = lo;
    }
}

// -------- kernel 3 (hot): mma.sync bf16 3-split v-GEMM + loc-GEMM --------
#define SROW   144
#define TILE_B (128*SROW)
#define OFF_A(buf,part) ((uint32_t)(((buf)*2+(part))*TILE_B))
#define OFF_B(buf,part) ((uint32_t)(73728u + ((buf)*2+(part))*TILE_B))
#define OFF_EP 147456u
#define OFF_Q  149504u
#define OFF_WV 150016u
#define SMEM_DYN 150528

__global__ __launch_bounds__(256) void kmain(const float* __restrict__ value,
                                             const float* __restrict__ Wv) {
    extern __shared__ __align__(16) char sm[];
    uint32_t smu = (uint32_t)__cvta_generic_to_shared(sm);

    int tt  = blockIdx.x;
    int b   = blockIdx.y;
    int t0  = tt * 128;
    int tid = threadIdx.x;
    int lane = tid & 31;
    int wid  = tid >> 5;
    int wr   = wid >> 2;
    int wc   = wid & 3;
    int grp  = lane >> 2;
    int tig  = lane & 3;

    float* sq    = reinterpret_cast<float*>(sm + OFF_Q);
    float* sWv   = reinterpret_cast<float*>(sm + OFF_WV);
    float* epart = reinterpret_cast<float*>(sm + OFF_EP);

    if (tid < 128) { sq[tid] = g_q[b*A_ + tid]; sWv[tid] = Wv[tid]; }

    #pragma unroll
    for (int part = 0; part < 2; part++)
        #pragma unroll
        for (int r = 0; r < 4; r++) {
            int i = tid + r*256;
            int row = i >> 3, cc = i & 7;
            uint32_t doff = (uint32_t)(row*SROW + cc*16);
            CP16(smu + OFF_A(0, part) + doff, (const char*)&gCimg[part][tt][i*8]);
            CP16(smu + OFF_B(0, part) + doff, (const char*)&gSimg[part][b][i*8]);
        }
    CP_COMMIT();
    CP_WAIT0();
    __syncthreads();

    float accv[4][4][4];
    float accl[4][4][4];
    #pragma unroll
    for (int mt = 0; mt < 4; mt++)
        #pragma unroll
        for (int nt = 0; nt < 4; nt++)
            #pragma unroll
            for (int f = 0; f < 4; f++) { accv[mt][nt][f] = 0.f; accl[mt][nt][f] = 0.f; }

    int vrow = tid >> 1;
    int vkh  = tid & 1;
    const float* vbase = value + ((size_t)(b*T_) + t0 + vrow)*DV_ + vkh*32;

    auto compute_chunk = [&](float (&acc)[4][4][4], int pb) {
        uint32_t aH = OFF_A(pb, 0), aL = OFF_A(pb, 1);
        uint32_t bH = OFF_B(pb, 0), bL = OFF_B(pb, 1);
        #pragma unroll
        for (int kk = 0; kk < 4; kk++) {
            uint32_t Ah[4][4], Al[4][4];
            #pragma unroll
            for (int mt = 0; mt < 4; mt++)
                #pragma unroll
                for (int rg = 0; rg < 4; rg++) {
                    int row = wr*64 + mt*16 + grp + (rg & 1)*8;
                    int col = kk*16 + 2*tig + (rg >> 1)*8;
                    uint32_t off = (uint32_t)(row*SROW + col*2);
                    Ah[mt][rg] = *reinterpret_cast<const uint32_t*>(sm + aH + off);
                    Al[mt][rg] = *reinterpret_cast<const uint32_t*>(sm + aL + off);
                }
            #pragma unroll
            for (int nt = 0; nt < 4; nt++) {
                int nrow = wc*32 + nt*8 + grp;
                uint32_t off0 = (uint32_t)(nrow*SROW + (kk*16 + 2*tig)*2);
                uint32_t Bh0 = *reinterpret_cast<const uint32_t*>(sm + bH + off0);
                uint32_t Bh1 = *reinterpret_cast<const uint32_t*>(sm + bH + off0 + 16);
                uint32_t Bl0 = *reinterpret_cast<const uint32_t*>(sm + bL + off0);
                uint32_t Bl1 = *reinterpret_cast<const uint32_t*>(sm + bL + off0 + 16);
                #pragma unroll
                for (int mt = 0; mt < 4; mt++) {
                    mma4(acc[mt][nt], Ah[mt], Bh0, Bh1);
                    mma4(acc[mt][nt], Al[mt], Bh0, Bh1);
                    mma4(acc[mt][nt], Ah[mt], Bl0, Bl1);
                }
            }
        }
    };

    #pragma unroll 1
    for (int q = 0; q < 9; q++) {
        int pb = q & 1;
        int nb = (q + 1) & 1;
        float4 vf[8];
        if (q < 8) {
            #pragma unroll
            for (int part = 0; part < 2; part++)
                #pragma unroll
                for (int r = 0; r < 4; r++) {
                    int i = tid + r*256;
                    int row = i >> 3, cc = i & 7;
                    CP16(smu + OFF_B(nb, part) + (uint32_t)(row*SROW + cc*16),
                         (const char*)&gBimg[part][q][i*8]);
                }
            CP_COMMIT();
            const float* src = vbase + q*64;
            #pragma unroll
            for (int g = 0; g < 8; g++)
                vf[g] = *reinterpret_cast<const float4*>(src + g*4);
        }

        if (q == 0) compute_chunk(accl, pb);
        else        compute_chunk(accv, pb);

        if (q < 8) {
            char* dH = sm + OFF_A(nb, 0) + vrow*SROW + vkh*64;
            char* dL = sm + OFF_A(nb, 1) + vrow*SROW + vkh*64;
            #pragma unroll
            for (int g = 0; g < 4; g++) {
                float x[8];
                x[0] = vf[2*g].x;   x[1] = vf[2*g].y;
                x[2] = vf[2*g].z;   x[3] = vf[2*g].w;
                x[4] = vf[2*g+1].x; x[5] = vf[2*g+1].y;
                x[6] = vf[2*g+1].z; x[7] = vf[2*g+1].w;
                uint4 hi, lo;
                split8(x, hi, lo);
                *reinterpret_cast<uint4*>(dH + g*16) = hi;
                *reinterpret_cast<uint4*>(dL + g*16) = lo;
            }
        }
        CP_WAIT0();
        __syncthreads();
    }

    float qc[8], wv[8];
    #pragma unroll
    for (int nt = 0; nt < 4; nt++) {
        int c0 = wc*32 + nt*8 + 2*tig;
        qc[nt*2]   = sq[c0];     qc[nt*2+1] = sq[c0+1];
        wv[nt*2]   = sWv[c0];    wv[nt*2+1] = sWv[c0+1];
    }

    #pragma unroll
    for (int mt = 0; mt < 4; mt++) {
        #pragma unroll
        for (int h = 0; h < 2; h++) {
            int row = wr*64 + mt*16 + grp + h*8;
            int t = t0 + row;
            float pe = 0.0f;
            #pragma unroll
            for (int nt = 0; nt < 4; nt++) {
                float v0 = ftanh(accv[mt][nt][h*2 + 0]);
                float v1 = ftanh(accv[mt][nt][h*2 + 1]);
                float l0 = ftanh(accl[mt][nt][h*2 + 0]);
                float l1 = ftanh(accl[mt][nt][h*2 + 1]);
                int c0 = wc*32 + nt*8 + 2*tig;
                __half2 hv = __floats2half2_rn(v0, v1);
                *reinterpret_cast<__half2*>(&g_vh[((size_t)b*T_ + t)*A_ + c0]) = hv;
                pe += ftanh(qc[nt*2]   + v0 + l0) * wv[nt*2];
                pe += ftanh(qc[nt*2+1] + v1 + l1) * wv[nt*2+1];
            }
            pe += __shfl_xor_sync(0xffffffffu, pe, 1);
            pe += __shfl_xor_sync(0xffffffffu, pe, 2);
            if (tig == 0) epart[row*4 + wc] = pe;
        }
    }
    __syncthreads();
    if (tid < 128) {
        float e = epart[tid*4+0] + epart[tid*4+1] + epart[tid*4+2] + epart[tid*4+3];
        g_e[b*T_ + t0 + tid] = e;
    }
}

// ------- kernel 4: softmax over T + context (512 thr, half2 v) -------
__global__ __launch_bounds__(512) void kctx(float* __restrict__ out) {
    int b = blockIdx.x;
    int tid = threadIdx.x;
    __shared__ float p[T_];
    __shared__ float red[16];
    __shared__ float cpart[8][A_];

    float e0 = g_e[b*T_ + tid];
    float e1 = g_e[b*T_ + tid + 512];
    float m = fmaxf(e0, e1);
    #pragma unroll
    for (int o = 16; o; o >>= 1) m = fmaxf(m, __shfl_xor_sync(0xffffffffu, m, o));
    if ((tid & 31) == 0) red[tid >> 5] = m;
    __syncthreads();
    if (tid < 32) {
        float mm = (tid < 16) ? red[tid] : -3.0e38f;
        #pragma unroll
        for (int o = 8; o; o >>= 1) mm = fmaxf(mm, __shfl_xor_sync(0xffffffffu, mm, o));
        if (tid == 0) red[0] = mm;
    }
    __syncthreads();
    m = red[0];
    __syncthreads();

    float x0 = __expf(e0 - m);
    float x1 = __expf(e1 - m);
    float s = x0 + x1;
    #pragma unroll
    for (int o = 16; o; o >>= 1) s += __shfl_xor_sync(0xffffffffu, s, o);
    if ((tid & 31) == 0) red[tid >> 5] = s;
    __syncthreads();
    if (tid < 32) {
        float ss = (tid < 16) ? red[tid] : 0.0f;
        #pragma unroll
        for (int o = 8; o; o >>= 1) ss += __shfl_xor_sync(0xffffffffu, ss, o);
        if (tid == 0) red[0] = ss;
    }
    __syncthreads();
    float inv = 1.0f / red[0];

    float p0 = x0 * inv, p1 = x1 * inv;
    p[tid]       = p0;
    p[tid + 512] = p1;
    out[B_*A_ + b*T_ + tid]       = p0;
    out[B_*A_ + b*T_ + tid + 512] = p1;
    __syncthreads();

    int g  = tid >> 6;
    int a2 = tid & 63;
    const __half2* vp = reinterpret_cast<const __half2*>(g_vh)
                        + ((size_t)b*T_ + (size_t)g*128)*64 + a2;
    float accx = 0.0f, accy = 0.0f;
    #pragma unroll 8
    for (int t = 0; t < 128; t++) {
        float2 vv = __half22float2(vp[(size_t)t*64]);
        float pt = p[g*128 + t];
        accx = fmaf(pt, vv.x, accx);
        accy = fmaf(pt, vv.y, accy);
    }
    cpart[g][2*a2]     = accx;
    cpart[g][2*a2 + 1] = accy;
    __syncthreads();
    if (tid < A_) {
        float c = 0.0f;
        #pragma unroll
        for (int gg = 0; gg < 8; gg++) c += cpart[gg][tid];
        out[b*A_ + tid] = c;
    }
}

// ---------------- launcher ----------------
extern "C" void kernel_launch(void* const* d_in, const int* in_sizes, int n_in,
                              void* d_out, int out_size) {
    const float* query = (const float*)d_in[0];
    const float* value = (const float*)d_in[1];
    const float* awcat = (const float*)d_in[2];
    const float* Wq    = (const float*)d_in[3];
    const float* Wm    = (const float*)d_in[4];
    const float* Wv    = (const float*)d_in[5];
    const float* Wconv = (const float*)d_in[6];
    const float* Wloc  = (const float*)d_in[7];
    float* out = (float*)d_out;

    static bool attr_set = false;
    if (!attr_set) {
        cudaFuncSetAttribute(kmain, cudaFuncAttributeMaxDynamicSharedMemorySize, SMEM_DYN);
        attr_set = true;
    }

    kstage1<<< S1_TOT, 128 >>>(query, Wq, Wm, Wconv, awcat, Wloc);
    kstage2<<< B_, 128 >>>();
    kmain  <<< dim3(NTT, B_), 256, SMEM_DYN >>>(value, Wv);
    kctx   <<< B_, 512 >>>(out);
}

// round 13
// speedup vs baseline: 2.1742x; 1.0875x over previous
#include <cuda_runtime.h>
#include <cuda_fp16.h>
#include <cuda_bf16.h>
#include <cstdint>

#define B_  64
#define T_  1024
#define A_  128
#define F_  1024
#define KC_ 31
#define DQ_ 1024
#define DV_ 512
#define J_  62
#define NCS 8           // kS t-chunks
#define TCS 128         // t per chunk
#define NTT 8           // t-tiles of 128
#define NCH 8           // k-chunks of 64
#define CHK 8192        // elems per bf16 image chunk (128 x 64)

// ---- scratch (device globals) ----
__device__ __half g_vh[B_*T_*A_];
__device__ float g_q [B_*A_];
__device__ float g_qp[256*A_];
__device__ float g_e [B_*T_];
__device__ float g_Sp[B_*NCS*J_*A_];
__device__ __align__(16) __nv_bfloat16 gBimg[2][NCH][CHK];  // Wm^T   (row=a)
__device__ __align__(16) __nv_bfloat16 gCimg[2][NTT][CHK];  // Wconv^T(row=t_local)
__device__ __align__(16) __nv_bfloat16 gSimg[2][B_ ][CHK];  // S^T    (row=a)

__device__ __forceinline__ float ftanh(float x) {
    float e = __expf(2.0f * x);
    return 1.0f - __fdividef(2.0f, e + 1.0f);
}

__device__ __forceinline__ void split8(const float* x, uint4& hi, uint4& lo) {
    unsigned hw[4], lw[4];
    #pragma unroll
    for (int p = 0; p < 4; p++) {
        __nv_bfloat162 h = __floats2bfloat162_rn(x[2*p], x[2*p+1]);
        float r0 = x[2*p]   - __low2float(h);
        float r1 = x[2*p+1] - __high2float(h);
        __nv_bfloat162 l = __floats2bfloat162_rn(r0, r1);
        hw[p] = *reinterpret_cast<unsigned*>(&h);
        lw[p] = *reinterpret_cast<unsigned*>(&l);
    }
    hi = make_uint4(hw[0], hw[1], hw[2], hw[3]);
    lo = make_uint4(lw[0], lw[1], lw[2], lw[3]);
}

#define CP16(dst_u32, src_ptr) \
    asm volatile("cp.async.ca.shared.global [%0], [%1], 16;" \
                 :: "r"(dst_u32), "l"(src_ptr) : "memory")
#define CP_COMMIT() asm volatile("cp.async.commit_group;" ::: "memory")
#define CP_WAIT0()  asm volatile("cp.async.wait_group 0;" ::: "memory")

#define LDSM4(r, addr) \
    asm volatile("ldmatrix.sync.aligned.m8n8.x4.shared.b16 {%0,%1,%2,%3}, [%4];" \
        : "=r"((r)[0]), "=r"((r)[1]), "=r"((r)[2]), "=r"((r)[3]) : "r"(addr))

__device__ __forceinline__ void mma4(float* c, const uint32_t* a,
                                     uint32_t b0, uint32_t b1) {
    asm volatile(
        "mma.sync.aligned.m16n8k16.row.col.f32.bf16.bf16.f32 "
        "{%0,%1,%2,%3},{%4,%5,%6,%7},{%8,%9},{%0,%1,%2,%3};"
        : "+f"(c[0]), "+f"(c[1]), "+f"(c[2]), "+f"(c[3])
        : "r"(a[0]), "r"(a[1]), "r"(a[2]), "r"(a[3]), "r"(b0), "r"(b1));
}

// =============== stage 1: kq-partials | prepB | prepC | kS (fused) ===============
#define S1_KQ   256
#define S1_PB   (S1_KQ + NCH)
#define S1_PC   (S1_PB + NTT)
#define S1_TOT  (S1_PC + B_*NCS)

__global__ __launch_bounds__(128) void kstage1(const float* __restrict__ query,
                                               const float* __restrict__ Wq,
                                               const float* __restrict__ Wm,
                                               const float* __restrict__ Wconv,
                                               const float* __restrict__ aw,
                                               const float* __restrict__ Wloc) {
    int blk = blockIdx.x;
    int tid = threadIdx.x;

    if (blk < S1_KQ) {
        int b = blk >> 2, qq = blk & 3;
        __shared__ float qs[256];
        qs[tid]       = query[b*DQ_ + qq*256 + tid];
        qs[tid + 128] = query[b*DQ_ + qq*256 + 128 + tid];
        __syncthreads();
        float acc = 0.0f;
        #pragma unroll 8
        for (int d = 0; d < 256; d++)
            acc = fmaf(qs[d], Wq[(size_t)(qq*256 + d)*A_ + tid], acc);
        g_qp[blk*A_ + tid] = acc;
    } else if (blk < S1_PB) {
        int c = blk - S1_KQ;
        #pragma unroll 1
        for (int k8 = 0; k8 < 8; k8++) {
            float x[8];
            #pragma unroll
            for (int i = 0; i < 8; i++)
                x[i] = Wm[(size_t)(c*64 + k8*8 + i)*A_ + tid];
            uint4 hi, lo;
            split8(x, hi, lo);
            *reinterpret_cast<uint4*>(&gBimg[0][c][tid*64 + k8*8]) = hi;
            *reinterpret_cast<uint4*>(&gBimg[1][c][tid*64 + k8*8]) = lo;
        }
    } else if (blk < S1_PC) {
        int tt = blk - S1_PB;
        #pragma unroll 1
        for (int k8 = 0; k8 < 8; k8++) {
            float x[8];
            #pragma unroll
            for (int i = 0; i < 8; i++) {
                int j = k8*8 + i;
                x[i] = (j < J_) ? Wconv[(size_t)j*F_ + tt*128 + tid] : 0.0f;
            }
            uint4 hi, lo;
            split8(x, hi, lo);
            *reinterpret_cast<uint4*>(&gCimg[0][tt][tid*64 + k8*8]) = hi;
            *reinterpret_cast<uint4*>(&gCimg[1][tt][tid*64 + k8*8]) = lo;
        }
    } else {
        int i  = blk - S1_PC;
        int b  = i >> 3;
        int ch = i & 7;
        int t0 = ch * TCS;

        __shared__ float2 awm2[TCS + KC_ - 1];
        for (int idx = tid; idx < TCS + KC_ - 1; idx += 128) {
            int t = t0 + idx - 15;
            float2 v = make_float2(0.0f, 0.0f);
            if (t >= 0 && t < T_) {
                v.x = aw[(b*T_ + t)*2 + 0];
                v.y = aw[(b*T_ + t)*2 + 1];
            }
            awm2[idx] = v;
        }
        __syncthreads();

        unsigned long long acc2[KC_];
        #pragma unroll
        for (int k = 0; k < KC_; k++) acc2[k] = 0ull;

        #pragma unroll 1
        for (int tl = 0; tl < TCS; tl++) {
            float w = Wloc[(size_t)(t0 + tl)*A_ + tid];
            unsigned long long wd;
            asm("mov.b64 %0, {%1,%1};" : "=l"(wd) : "f"(w));
            #pragma unroll
            for (int k = 0; k < KC_; k++) {
                unsigned long long bv = *reinterpret_cast<const unsigned long long*>(&awm2[tl + k]);
                asm("fma.rn.f32x2 %0, %1, %2, %0;" : "+l"(acc2[k]) : "l"(wd), "l"(bv));
            }
        }
        float* dst = &g_Sp[((size_t)(b*NCS + ch)*J_)*A_ + tid];
        #pragma unroll
        for (int k = 0; k < KC_; k++) {
            dst[(2*k    )*A_] = __uint_as_float((unsigned)(acc2[k] & 0xffffffffu));
            dst[(2*k + 1)*A_] = __uint_as_float((unsigned)(acc2[k] >> 32));
        }
    }
}

// =============== stage 2: finalize q + reduce S -> bf16 images ===============
__global__ __launch_bounds__(128) void kstage2() {
    int b = blockIdx.x;
    int a = threadIdx.x;

    float qa = g_qp[(b*4+0)*A_ + a] + g_qp[(b*4+1)*A_ + a]
             + g_qp[(b*4+2)*A_ + a] + g_qp[(b*4+3)*A_ + a];
    g_q[b*A_ + a] = ftanh(qa);

    const float* part = &g_Sp[(size_t)(b*NCS)*J_*A_ + a];
    #pragma unroll 1
    for (int j8 = 0; j8 < 8; j8++) {
        float x[8];
        #pragma unroll
        for (int i = 0; i < 8; i++) {
            int j = j8*8 + i;
            float s = 0.0f;
            if (j < J_) {
                #pragma unroll
                for (int ch = 0; ch < NCS; ch++)
                    s += part[((size_t)ch*J_ + j)*A_];
            }
            x[i] = s;
        }
        uint4 hi, lo;
        split8(x, hi, lo);
        *reinterpret_cast<uint4*>(&gSimg[0][b][a*64 + j8*8]) = hi;
        *reinterpret_cast<uint4*>(&gSimg[1][b][a*64 + j8*8]) = lo;
    }
}

// -------- kernel 3 (hot): mma.sync bf16 3-split, ldmatrix, cp.async value --------
#define SROW   144
#define TILE_B (128*SROW)               // 18432
#define OFF_A(buf,part) ((uint32_t)(((buf)*2+(part))*TILE_B))
#define OFF_B(buf,part) ((uint32_t)(73728u + ((buf)*2+(part))*TILE_B))
#define OFF_V  147456u                  // value fp32 stage: 128 rows x 288B
#define OFF_LT 184320u                  // ltanh: 128 rows x 132 halfs
#define OFF_EP 218112u
#define OFF_Q  220160u
#define OFF_WV 220672u
#define SMEM_DYN 221184

__global__ __launch_bounds__(256) void kmain(const float* __restrict__ value,
                                             const float* __restrict__ Wv) {
    extern __shared__ __align__(16) char sm[];
    uint32_t smu = (uint32_t)__cvta_generic_to_shared(sm);

    int tt  = blockIdx.x;
    int b   = blockIdx.y;
    int t0  = tt * 128;
    int tid = threadIdx.x;
    int lane = tid & 31;
    int wid  = tid >> 5;
    int wr   = wid >> 2;             // 0..1 row-group
    int wc   = wid & 3;              // 0..3 col-group
    int grp  = lane >> 2;
    int tig  = lane & 3;
    int oct  = lane >> 3;            // ldmatrix octet
    int orow = lane & 7;

    float*   sq    = reinterpret_cast<float*>(sm + OFF_Q);
    float*   sWv   = reinterpret_cast<float*>(sm + OFF_WV);
    float*   epart = reinterpret_cast<float*>(sm + OFF_EP);
    __half2* lth   = reinterpret_cast<__half2*>(sm + OFF_LT);  // stride 66 half2/row
    float*   Vst   = reinterpret_cast<float*>(sm + OFF_V);     // stride 72 floats/row

    if (tid < 128) { sq[tid] = g_q[b*A_ + tid]; sWv[tid] = Wv[tid]; }

    // ldmatrix per-lane byte offsets
    uint32_t aoff = (uint32_t)((wr*64 + (oct & 1)*8 + orow)*SROW + (oct >> 1)*16);
    uint32_t boff = (uint32_t)((wc*32 + (oct >> 1)*8 + orow)*SROW + (oct & 1)*16);

    // prologue: stage loc operands (Wconv^T -> A0, S^T -> B0)
    #pragma unroll
    for (int part = 0; part < 2; part++)
        #pragma unroll
        for (int r = 0; r < 4; r++) {
            int i = tid + r*256;
            int row = i >> 3, cc = i & 7;
            uint32_t doff = (uint32_t)(row*SROW + cc*16);
            CP16(smu + OFF_A(0, part) + doff, (const char*)&gCimg[part][tt][i*8]);
            CP16(smu + OFF_B(0, part) + doff, (const char*)&gSimg[part][b][i*8]);
        }
    CP_COMMIT();
    CP_WAIT0();
    __syncthreads();

    float acc[4][4][4];
    #pragma unroll
    for (int mt = 0; mt < 4; mt++)
        #pragma unroll
        for (int nt = 0; nt < 4; nt++)
            #pragma unroll
            for (int f = 0; f < 4; f++) acc[mt][nt][f] = 0.f;

    int vrow = tid >> 1;             // conversion row
    int vkh  = tid & 1;

    auto compute_chunk = [&](int pb) {
        uint32_t aH = smu + OFF_A(pb, 0) + aoff;
        uint32_t aL = smu + OFF_A(pb, 1) + aoff;
        uint32_t bHa = smu + OFF_B(pb, 0) + boff;
        uint32_t bLa = smu + OFF_B(pb, 1) + boff;
        #pragma unroll
        for (int kk = 0; kk < 4; kk++) {
            uint32_t Ah[4][4], Al[4][4];
            #pragma unroll
            for (int mt = 0; mt < 4; mt++) {
                uint32_t ad = aH + (uint32_t)(mt*16*SROW + kk*32);
                LDSM4(Ah[mt], ad);
                LDSM4(Al[mt], ad + (aL - aH));
            }
            uint32_t Bh[4][2], Bl[4][2];
            #pragma unroll
            for (int ntp = 0; ntp < 2; ntp++) {
                uint32_t bd = bHa + (uint32_t)(ntp*16*SROW + kk*32);
                uint32_t r4[4];
                LDSM4(r4, bd);
                Bh[2*ntp][0] = r4[0]; Bh[2*ntp][1] = r4[1];
                Bh[2*ntp+1][0] = r4[2]; Bh[2*ntp+1][1] = r4[3];
                LDSM4(r4, bd + (bLa - bHa));
                Bl[2*ntp][0] = r4[0]; Bl[2*ntp][1] = r4[1];
                Bl[2*ntp+1][0] = r4[2]; Bl[2*ntp+1][1] = r4[3];
            }
            #pragma unroll
            for (int nt = 0; nt < 4; nt++)
                #pragma unroll
                for (int mt = 0; mt < 4; mt++) {
                    mma4(acc[mt][nt], Ah[mt], Bh[nt][0], Bh[nt][1]);
                    mma4(acc[mt][nt], Al[mt], Bh[nt][0], Bh[nt][1]);
                    mma4(acc[mt][nt], Ah[mt], Bl[nt][0], Bl[nt][1]);
                }
        }
    };

    #pragma unroll 1
    for (int q = 0; q < 9; q++) {
        int pb = q & 1;
        int nb = (q + 1) & 1;
        if (q < 8) {
            // stage Wm^T chunk q -> B[nb]
            #pragma unroll
            for (int part = 0; part < 2; part++)
                #pragma unroll
                for (int r = 0; r < 4; r++) {
                    int i = tid + r*256;
                    int row = i >> 3, cc = i & 7;
                    CP16(smu + OFF_B(nb, part) + (uint32_t)(row*SROW + cc*16),
                         (const char*)&gBimg[part][q][i*8]);
                }
            // stage value fp32 chunk q -> Vstage
            #pragma unroll
            for (int r = 0; r < 8; r++) {
                int p = tid + r*256;
                int row = p >> 4, pc = p & 15;
                int h = pc >> 3, cc = pc & 7;
                CP16(smu + OFF_V + (uint32_t)(row*288 + h*144 + cc*16),
                     (const char*)(value + ((size_t)(b*T_ + t0 + row)*DV_
                                            + q*64 + h*32 + cc*4)));
            }
            CP_COMMIT();
        }

        compute_chunk(pb);

        if (q == 0) {
            // park tanh(loc) in smem as half2, free accumulators
            #pragma unroll
            for (int mt = 0; mt < 4; mt++)
                #pragma unroll
                for (int nt = 0; nt < 4; nt++)
                    #pragma unroll
                    for (int h = 0; h < 2; h++) {
                        int row = wr*64 + mt*16 + grp + h*8;
                        lth[row*66 + wc*16 + nt*4 + tig] =
                            __floats2half2_rn(ftanh(acc[mt][nt][h*2]),
                                              ftanh(acc[mt][nt][h*2+1]));
                    }
            #pragma unroll
            for (int mt = 0; mt < 4; mt++)
                #pragma unroll
                for (int nt = 0; nt < 4; nt++)
                    #pragma unroll
                    for (int f = 0; f < 4; f++) acc[mt][nt][f] = 0.f;
        }

        if (q < 8) {
            CP_WAIT0();
            __syncthreads();
            // convert Vstage -> A[nb] bf16 hi/lo
            const float* src = Vst + vrow*72 + vkh*36;
            char* dH = sm + OFF_A(nb, 0) + vrow*SROW + vkh*64;
            char* dL = sm + OFF_A(nb, 1) + vrow*SROW + vkh*64;
            #pragma unroll
            for (int g = 0; g < 4; g++) {
                float x[8];
                float4 f0 = *reinterpret_cast<const float4*>(src + g*8);
                float4 f1 = *reinterpret_cast<const float4*>(src + g*8 + 4);
                x[0]=f0.x; x[1]=f0.y; x[2]=f0.z; x[3]=f0.w;
                x[4]=f1.x; x[5]=f1.y; x[6]=f1.z; x[7]=f1.w;
                uint4 hi, lo;
                split8(x, hi, lo);
                *reinterpret_cast<uint4*>(dH + g*16) = hi;
                *reinterpret_cast<uint4*>(dL + g*16) = lo;
            }
        }
        __syncthreads();
    }

    // ---- epilogue ----
    float qc[8], wv[8];
    #pragma unroll
    for (int nt = 0; nt < 4; nt++) {
        int c0 = wc*32 + nt*8 + 2*tig;
        qc[nt*2]   = sq[c0];     qc[nt*2+1] = sq[c0+1];
        wv[nt*2]   = sWv[c0];    wv[nt*2+1] = sWv[c0+1];
    }

    #pragma unroll
    for (int mt = 0; mt < 4; mt++) {
        #pragma unroll
        for (int h = 0; h < 2; h++) {
            int row = wr*64 + mt*16 + grp + h*8;
            int t = t0 + row;
            float pe = 0.0f;
            #pragma unroll
            for (int nt = 0; nt < 4; nt++) {
                float v0 = ftanh(acc[mt][nt][h*2 + 0]);
                float v1 = ftanh(acc[mt][nt][h*2 + 1]);
                float2 lt = __half22float2(lth[row*66 + wc*16 + nt*4 + tig]);
                int c0 = wc*32 + nt*8 + 2*tig;
                __half2 hv = __floats2half2_rn(v0, v1);
                *reinterpret_cast<__half2*>(&g_vh[((size_t)b*T_ + t)*A_ + c0]) = hv;
                pe += ftanh(qc[nt*2]   + v0 + lt.x) * wv[nt*2];
                pe += ftanh(qc[nt*2+1] + v1 + lt.y) * wv[nt*2+1];
            }
            pe += __shfl_xor_sync(0xffffffffu, pe, 1);
            pe += __shfl_xor_sync(0xffffffffu, pe, 2);
            if (tig == 0) epart[row*4 + wc] = pe;
        }
    }
    __syncthreads();
    if (tid < 128) {
        float e = epart[tid*4+0] + epart[tid*4+1] + epart[tid*4+2] + epart[tid*4+3];
        g_e[b*T_ + t0 + tid] = e;
    }
}

// ------- kernel 4: softmax over T + context (1024 thr, 16 t-groups) -------
__global__ __launch_bounds__(1024) void kctx(float* __restrict__ out) {
    int b = blockIdx.x;
    int tid = threadIdx.x;
    __shared__ float p[T_];
    __shared__ float red[32];
    __shared__ float cpart[16][A_];

    float e = g_e[b*T_ + tid];
    float m = e;
    #pragma unroll
    for (int o = 16; o; o >>= 1) m = fmaxf(m, __shfl_xor_sync(0xffffffffu, m, o));
    if ((tid & 31) == 0) red[tid >> 5] = m;
    __syncthreads();
    if (tid < 32) {
        float mm = red[tid];
        #pragma unroll
        for (int o = 16; o; o >>= 1) mm = fmaxf(mm, __shfl_xor_sync(0xffffffffu, mm, o));
        if (tid == 0) red[0] = mm;
    }
    __syncthreads();
    m = red[0];
    __syncthreads();

    float x = __expf(e - m);
    float s = x;
    #pragma unroll
    for (int o = 16; o; o >>= 1) s += __shfl_xor_sync(0xffffffffu, s, o);
    if ((tid & 31) == 0) red[tid >> 5] = s;
    __syncthreads();
    if (tid < 32) {
        float ss = red[tid];
        #pragma unroll
        for (int o = 16; o; o >>= 1) ss += __shfl_xor_sync(0xffffffffu, ss, o);
        if (tid == 0) red[0] = ss;
    }
    __syncthreads();
    float inv = 1.0f / red[0];

    float pv = x * inv;
    p[tid] = pv;
    out[B_*A_ + b*T_ + tid] = pv;
    __syncthreads();

    int g  = tid >> 6;               // 0..15, 64 t each
    int a2 = tid & 63;
    const __half2* vp = reinterpret_cast<const __half2*>(g_vh)
                        + ((size_t)b*T_ + (size_t)g*64)*64 + a2;
    float accx = 0.0f, accy = 0.0f;
    #pragma unroll 8
    for (int t = 0; t < 64; t++) {
        float2 vv = __half22float2(vp[(size_t)t*64]);
        float pt = p[g*64 + t];
        accx = fmaf(pt, vv.x, accx);
        accy = fmaf(pt, vv.y, accy);
    }
    cpart[g][2*a2]     = accx;
    cpart[g][2*a2 + 1] = accy;
    __syncthreads();
    if (tid < A_) {
        float c = 0.0f;
        #pragma unroll
        for (int gg = 0; gg < 16; gg++) c += cpart[gg][tid];
        out[b*A_ + tid] = c;
    }
}

// ---------------- launcher ----------------
extern "C" void kernel_launch(void* const* d_in, const int* in_sizes, int n_in,
                              void* d_out, int out_size) {
    const float* query = (const float*)d_in[0];
    const float* value = (const float*)d_in[1];
    const float* awcat = (const float*)d_in[2];
    const float* Wq    = (const float*)d_in[3];
    const float* Wm    = (const float*)d_in[4];
    const float* Wv    = (const float*)d_in[5];
    const float* Wconv = (const float*)d_in[6];
    const float* Wloc  = (const float*)d_in[7];
    float* out = (float*)d_out;

    static bool attr_set = false;
    if (!attr_set) {
        cudaFuncSetAttribute(kmain, cudaFuncAttributeMaxDynamicSharedMemorySize, SMEM_DYN);
        attr_set = true;
    }

    kstage1<<< S1_TOT, 128 >>>(query, Wq, Wm, Wconv, awcat, Wloc);
    kstage2<<< B_, 128 >>>();
    kmain  <<< dim3(NTT, B_), 256, SMEM_DYN >>>(value, Wv);
    kctx   <<< B_, 1024 >>>(out);
}